// round 7
// baseline (speedup 1.0000x reference)
#include <cuda_runtime.h>
#include <cuda_fp16.h>
#include <cstdint>

// ---------------------------------------------------------------------------
// CloudCrop via mma.sync fp16 single-product, 512-thread CTA (4 warps/SMSP
// for latency hiding). One CTA = 4 points (M=128), N=256, K=576/256.
// 16 warps in 4x4 grid, warp tile 32x64; warp M-row == point id.
// ---------------------------------------------------------------------------

#define Bc 4
#define Nc 1024
#define NS 32
#define CIN 512
#define C0 515
#define RADIUSf 0.05f
#define HMINf (-0.02f)
#define HMAXf 0.04f

#define KROWB 144             // A/W tile row bytes (64 fp16 + 16B pad)
#define CH1 9                 // layer-1 chunks of K=64 (K=576; chunk 8 = rel+pad)
#define CH2 4                 // layer-2 chunks (K=256)
#define A2ROWB 528            // y1 row bytes (256 fp16 + 16B pad)
#define A1BUF 18432           // 128 rows * 144B
#define WBUF  36864           // 256 rows * 144B
#define NTHR 512

// smem offsets (dynamic)
#define SM_A2    0            // 128 x 528 = 67584
#define SM_A1    0            // 2 x 18432 (overlays A2; dead until L1 epilogue)
#define SM_W     67584        // 2 x 36864
#define SM_B1    141312
#define SM_B2    142336
#define SM_LIDX  143360
#define SMEM_TOTAL 143872

// __device__ scratch (allocation-free), 16B-aligned
__device__ __align__(16) unsigned short d_fh[Bc * Nc * CIN];   // feat fp16 [b][n][c]
__device__ __align__(16) int            d_idx[Bc * Nc * NS];
__device__ __align__(16) float          d_rel[Bc * Nc * NS * 3];
__device__ __align__(16) unsigned short d_w1[CH1 * 256 * 64];  // [t][o][64] fp16
__device__ __align__(16) unsigned short d_w2[CH2 * 256 * 64];
__device__ __align__(16) float          d_bias1[256];
__device__ __align__(16) float          d_bias2[256];

__device__ __forceinline__ uint32_t s2u(const void* p) {
    uint32_t a;
    asm("{ .reg .u64 t; cvta.to.shared.u64 t, %1; cvt.u32.u64 %0, t; }" : "=r"(a) : "l"(p));
    return a;
}
__device__ __forceinline__ void cpa16(uint32_t dst, const void* src) {
    asm volatile("cp.async.cg.shared.global [%0], [%1], 16;" :: "r"(dst), "l"(src));
}
#define CP_COMMIT()  asm volatile("cp.async.commit_group;" ::: "memory")
#define CP_WAIT0()   asm volatile("cp.async.wait_group 0;" ::: "memory")

__device__ __forceinline__ void ldsm4(uint32_t& r0, uint32_t& r1, uint32_t& r2, uint32_t& r3,
                                      uint32_t addr) {
    asm volatile("ldmatrix.sync.aligned.m8n8.x4.shared.b16 {%0,%1,%2,%3}, [%4];"
                 : "=r"(r0), "=r"(r1), "=r"(r2), "=r"(r3) : "r"(addr));
}
#define MMA(d, A, b0r, b1r) \
    asm volatile("mma.sync.aligned.m16n8k16.row.col.f32.f16.f16.f32 " \
                 "{%0,%1,%2,%3},{%4,%5,%6,%7},{%8,%9},{%0,%1,%2,%3};" \
                 : "+f"((d).x), "+f"((d).y), "+f"((d).z), "+f"((d).w) \
                 : "r"((A)[0]), "r"((A)[1]), "r"((A)[2]), "r"((A)[3]), \
                   "r"(b0r), "r"(b1r))

// One k16 step for a 32x64 warp tile: 2 A-ldsm + 4 B-ldsm, 16 HMMA
template<int AROW>
__device__ __forceinline__ void gemm_kstep(float4 (&acc)[2][8], uint32_t a, uint32_t wb)
{
    uint32_t Ax[2][4], Bf[4][4];
    #pragma unroll
    for (int mt = 0; mt < 2; mt++)
        ldsm4(Ax[mt][0], Ax[mt][1], Ax[mt][2], Ax[mt][3], a + mt * 16 * AROW);
    #pragma unroll
    for (int p = 0; p < 4; p++)
        ldsm4(Bf[p][0], Bf[p][1], Bf[p][2], Bf[p][3], wb + p * 16 * KROWB);
    #pragma unroll
    for (int mt = 0; mt < 2; mt++) {
        #pragma unroll
        for (int p = 0; p < 4; p++) {
            MMA(acc[mt][2*p],   Ax[mt], Bf[p][0], Bf[p][1]);
            MMA(acc[mt][2*p+1], Ax[mt], Bf[p][2], Bf[p][3]);
        }
    }
}

// ---------------------------------------------------------------------------
// Prep: fold BN into weights -> fp16 rn, chunked layout [t][o][64].
// Column map: c<512 -> w1 col c+3 (features); 512..514 -> w1 cols 0..2 (rel).
// ---------------------------------------------------------------------------
__global__ void prep_w(const float* __restrict__ w1,
                       const float* __restrict__ g1, const float* __restrict__ b1,
                       const float* __restrict__ m1, const float* __restrict__ v1,
                       const float* __restrict__ w2,
                       const float* __restrict__ g2, const float* __restrict__ b2,
                       const float* __restrict__ m2, const float* __restrict__ v2)
{
    int i = blockIdx.x * blockDim.x + threadIdx.x;
    const int W1E = CH1 * 256 * 64;   // 147456
    const int W2E = CH2 * 256 * 64;   // 65536
    if (i < W1E) {
        int t = i >> 14, rem = i & 16383, o = rem >> 6, k = rem & 63;
        int c = t * 64 + k;
        float s = g1[o] * rsqrtf(v1[o] + 1e-5f);
        float val = 0.f;
        if (c < 512)      val = w1[o * C0 + c + 3] * s;
        else if (c < 515) val = w1[o * C0 + (c - 512)] * s;
        d_w1[i] = __half_as_ushort(__float2half_rn(val));
    }
    int j = i - W1E;
    if (j >= 0 && j < W2E) {
        int t = j >> 14, rem = j & 16383, o = rem >> 6, k = rem & 63;
        float s = g2[o] * rsqrtf(v2[o] + 1e-5f);
        d_w2[j] = __half_as_ushort(__float2half_rn(w2[o * 256 + t * 64 + k] * s));
    }
    if (i < 256) {
        float s1 = g1[i] * rsqrtf(v1[i] + 1e-5f);
        d_bias1[i] = b1[i] - m1[i] * s1;
        float s2 = g2[i] * rsqrtf(v2[i] + 1e-5f);
        d_bias2[i] = b2[i] - m2[i] * s2;
    }
}

// Transpose [B,512,N] -> point-major fp16 [B,N,512]
__global__ void transpose_feat(const float* __restrict__ f)
{
    __shared__ float tile[32][33];
    int b  = blockIdx.z;
    int c0 = blockIdx.y * 32;
    int n0 = blockIdx.x * 32;
    int tx = threadIdx.x, ty = threadIdx.y;
    const float* src = f + (size_t)b * CIN * Nc;
    #pragma unroll
    for (int k = 0; k < 32; k += 8)
        tile[ty + k][tx] = src[(c0 + ty + k) * Nc + n0 + tx];
    __syncthreads();
    size_t base = (size_t)b * Nc * CIN;
    #pragma unroll
    for (int k = 0; k < 32; k += 8) {
        float v = tile[tx][ty + k];
        d_fh[base + (size_t)(n0 + ty + k) * CIN + c0 + tx] =
            __half_as_ushort(__float2half_rn(v));
    }
}

__global__ void cylinder_query(const float* __restrict__ xyz,
                               const float* __restrict__ rot)
{
    __shared__ int sidx[4][NS];
    int w    = threadIdx.x >> 5;
    int lane = threadIdx.x & 31;
    int p = blockIdx.x * 4 + w;
    int b = p >> 10, n = p & 1023;

    const float* X = xyz + (size_t)b * Nc * 3;
    float cx = X[n * 3 + 0], cy = X[n * 3 + 1], cz = X[n * 3 + 2];
    const float* R = rot + (size_t)p * 9;
    float r00 = R[0], r01 = R[1], r02 = R[2];
    float r10 = R[3], r11 = R[4], r12 = R[5];
    float r20 = R[6], r21 = R[7], r22 = R[8];
    const float R2 = RADIUSf * RADIUSf;

    int cnt = 0;
    for (int m0 = 0; m0 < Nc; m0 += 32) {
        int m = m0 + lane;
        float dx = X[m * 3 + 0] - cx;
        float dy = X[m * 3 + 1] - cy;
        float dz = X[m * 3 + 2] - cz;
        float xr = r00 * dx + r01 * dy + r02 * dz;
        float yr = r10 * dx + r11 * dy + r12 * dz;
        float zr = r20 * dx + r21 * dy + r22 * dz;
        bool mk = (yr * yr + zr * zr < R2) && (xr > HMINf) && (xr < HMAXf);
        unsigned bal = __ballot_sync(0xffffffffu, mk);
        int pre = __popc(bal & ((1u << lane) - 1u));
        int slot = cnt + pre;
        if (mk && slot < NS) sidx[w][slot] = m;
        cnt += __popc(bal);
        if (cnt >= NS) break;
    }
    __syncwarp();
    int c32 = cnt < NS ? cnt : NS;
    int pad = (cnt > 0) ? sidx[w][0] : 0;
    int j = (lane < c32) ? sidx[w][lane] : pad;

    d_idx[p * NS + lane] = j;
    float dx = X[j * 3 + 0] - cx;
    float dy = X[j * 3 + 1] - cy;
    float dz = X[j * 3 + 2] - cz;
    float inv = 1.0f / RADIUSf;
    d_rel[(p * NS + lane) * 3 + 0] = (dx * r00 + dy * r10 + dz * r20) * inv;
    d_rel[(p * NS + lane) * 3 + 1] = (dx * r01 + dy * r11 + dz * r21) * inv;
    d_rel[(p * NS + lane) * 3 + 2] = (dx * r02 + dy * r12 + dz * r22) * inv;
}

// ---------------------------------------------------------------------------
// Main: one CTA = 4 points (M=128), N=256, 512 threads, 16 warps (4x4),
// warp tile 32x64 (warp M-row == point). cp.async 2-deep pipeline, K=64
// chunks; layer1 -> regs -> relu -> fp16 A2 -> layer2 -> maxpool.
// ---------------------------------------------------------------------------
__global__ void __launch_bounds__(NTHR, 1)
tc_mlp(float* __restrict__ out)
{
    extern __shared__ char smem[];
    uint32_t sb = s2u(smem);
    int tid  = threadIdx.x;
    int lane = tid & 31;
    int w    = tid >> 5;
    int wm   = w & 3;             // M index: point id within CTA, rows wm*32..
    int wn   = w >> 2;            // N index: cols wn*64..
    int blk  = blockIdx.x;
    int bb   = blk >> 8;
    int nbase = (blk & 255) * 4;

    float* bias1s = (float*)(smem + SM_B1);
    float* bias2s = (float*)(smem + SM_B2);
    int*   lidx   = (int*)(smem + SM_LIDX);

    if (tid < 128) lidx[tid] = d_idx[blk * 128 + tid];
    if (tid < 256) {
        bias1s[tid] = d_bias1[tid];
        bias2s[tid] = d_bias2[tid];
    }
    __syncthreads();

    const char* fbh = (const char*)d_fh + (size_t)bb * (Nc * CIN * 2);

    // lane-dependent fragment offsets
    uint32_t a1_off = (uint32_t)((wm * 32 + (lane & 15)) * KROWB + (lane >> 4) * 16);
    uint32_t a2_off = (uint32_t)((wm * 32 + (lane & 15)) * A2ROWB + (lane >> 4) * 16);
    uint32_t w_off  = (uint32_t)((wn * 64 + (lane & 7) + ((lane >> 4) << 3)) * KROWB
                                 + ((lane >> 3) & 1) * 16);

    // ---- prefetch helpers ----
    auto issue1 = [&](int t) {
        int buf = t & 1;
        if (t < 8) {
            #pragma unroll
            for (int it = 0; it < 2; it++) {
                int e = tid + it * NTHR;           // 0..1023
                int r = e >> 3, q = e & 7;
                uint32_t dst = sb + SM_A1 + (uint32_t)(buf * A1BUF + r * KROWB + q * 16);
                const char* srcb = fbh + (size_t)lidx[r] * 1024 + t * 128 + q * 16;
                cpa16(dst, srcb);
            }
        } else {
            // rel chunk: zero tile, then 3 real columns
            uint32_t* za = (uint32_t*)(smem + SM_A1 + buf * A1BUF);
            #pragma unroll
            for (int it = 0; it < 9; it++) za[tid + it * NTHR] = 0;
            if (tid < 128) {
                int r = tid;
                #pragma unroll
                for (int k = 0; k < 3; k++) {
                    float v = d_rel[(blk * 128 + r) * 3 + k];
                    *(unsigned short*)(smem + SM_A1 + buf * A1BUF + r * KROWB + k * 2) =
                        __half_as_ushort(__float2half_rn(v));
                }
            }
        }
        #pragma unroll
        for (int it = 0; it < 4; it++) {
            int e = tid + it * NTHR;               // 0..2047
            uint32_t dst = sb + SM_W + (uint32_t)((t & 1) * WBUF + (e >> 3) * KROWB + (e & 7) * 16);
            const char* srcb = (const char*)d_w1 + (size_t)t * 32768 + e * 16;
            cpa16(dst, srcb);
        }
        CP_COMMIT();
    };
    auto issue2 = [&](int t) {
        #pragma unroll
        for (int it = 0; it < 4; it++) {
            int e = tid + it * NTHR;
            uint32_t dst = sb + SM_W + (uint32_t)((t & 1) * WBUF + (e >> 3) * KROWB + (e & 7) * 16);
            const char* srcb = (const char*)d_w2 + (size_t)t * 32768 + e * 16;
            cpa16(dst, srcb);
        }
        CP_COMMIT();
    };

    float4 acc[2][8];
    #pragma unroll
    for (int mt = 0; mt < 2; mt++)
        #pragma unroll
        for (int nt = 0; nt < 8; nt++) acc[mt][nt] = make_float4(0.f, 0.f, 0.f, 0.f);

    // ================= layer 1 =================
    issue1(0);
    for (int t = 0; t < CH1; t++) {
        int buf = t & 1;
        CP_WAIT0();
        __syncthreads();
        if (t + 1 < CH1) issue1(t + 1);
        uint32_t a  = sb + SM_A1 + (uint32_t)(buf * A1BUF) + a1_off;
        uint32_t wb = sb + SM_W  + (uint32_t)(buf * WBUF)  + w_off;
        #pragma unroll
        for (int kk = 0; kk < 4; kk++)
            gemm_kstep<KROWB>(acc, a + kk * 32, wb + kk * 32);
    }
    __syncthreads();   // all warps done reading A1/W before A2 overlay writes

    // ---- layer-1 epilogue: bias+relu -> fp16 A2 ----
    {
        #pragma unroll
        for (int nt = 0; nt < 8; nt++) {
            int col0 = wn * 64 + nt * 8 + (lane & 3) * 2;
            float b0 = bias1s[col0], b1v = bias1s[col0 + 1];
            #pragma unroll
            for (int mt = 0; mt < 2; mt++) {
                float4 c = acc[mt][nt];
                int row0 = wm * 32 + mt * 16 + (lane >> 2);
                unsigned short h0 = __half_as_ushort(__float2half_rn(fmaxf(c.x + b0,  0.f)));
                unsigned short h1 = __half_as_ushort(__float2half_rn(fmaxf(c.y + b1v, 0.f)));
                *(uint32_t*)(smem + SM_A2 + row0 * A2ROWB + col0 * 2) = h0 | ((uint32_t)h1 << 16);
                h0 = __half_as_ushort(__float2half_rn(fmaxf(c.z + b0,  0.f)));
                h1 = __half_as_ushort(__float2half_rn(fmaxf(c.w + b1v, 0.f)));
                *(uint32_t*)(smem + SM_A2 + (row0 + 8) * A2ROWB + col0 * 2) = h0 | ((uint32_t)h1 << 16);
            }
        }
    }
    #pragma unroll
    for (int mt = 0; mt < 2; mt++)
        #pragma unroll
        for (int nt = 0; nt < 8; nt++) acc[mt][nt] = make_float4(0.f, 0.f, 0.f, 0.f);
    __syncthreads();

    // ================= layer 2 =================
    issue2(0);
    for (int t = 0; t < CH2; t++) {
        int buf = t & 1;
        CP_WAIT0();
        __syncthreads();
        if (t + 1 < CH2) issue2(t + 1);
        uint32_t a  = sb + SM_A2 + a2_off + (uint32_t)(t * 128);
        uint32_t wb = sb + SM_W + (uint32_t)(buf * WBUF) + w_off;
        #pragma unroll
        for (int kk = 0; kk < 4; kk++)
            gemm_kstep<A2ROWB>(acc, a + kk * 32, wb + kk * 32);
    }

    // ---- layer-2 epilogue: maxpool over point wm's 32 samples + bias + relu ----
    // Thread holds sample rows (lane>>2), +8 (within acc[mt]: .x/.y rows, .z/.w rows+8)
    // for m-tiles wm*32+mt*16. Reduce over lane bits 2..4 (8 threads sharing lane&3).
    #pragma unroll
    for (int nt = 0; nt < 8; nt++) {
        float4 c0 = acc[0][nt], c1 = acc[1][nt];
        float pa = fmaxf(fmaxf(c0.x, c0.z), fmaxf(c1.x, c1.z));   // col0
        float pb = fmaxf(fmaxf(c0.y, c0.w), fmaxf(c1.y, c1.w));   // col0+1
        #pragma unroll
        for (int off = 4; off < 32; off <<= 1) {
            pa = fmaxf(pa, __shfl_xor_sync(0xffffffffu, pa, off));
            pb = fmaxf(pb, __shfl_xor_sync(0xffffffffu, pb, off));
        }
        if (lane < 4) {
            int col0 = wn * 64 + nt * 8 + lane * 2;
            int n0 = nbase + wm;
            out[((size_t)bb * 256 + col0)     * 1024 + n0] = fmaxf(pa + bias2s[col0],     0.f);
            out[((size_t)bb * 256 + col0 + 1) * 1024 + n0] = fmaxf(pb + bias2s[col0 + 1], 0.f);
        }
    }
}

// ---------------------------------------------------------------------------
extern "C" void kernel_launch(void* const* d_in, const int* in_sizes, int n_in,
                              void* d_out, int out_size)
{
    const float* xyz  = (const float*)d_in[0];
    const float* feat = (const float*)d_in[1];
    const float* rot  = (const float*)d_in[2];
    const float* w1   = (const float*)d_in[3];
    const float* g1   = (const float*)d_in[4];
    const float* b1   = (const float*)d_in[5];
    const float* m1   = (const float*)d_in[6];
    const float* v1   = (const float*)d_in[7];
    const float* w2   = (const float*)d_in[8];
    const float* g2   = (const float*)d_in[9];
    const float* b2   = (const float*)d_in[10];
    const float* m2   = (const float*)d_in[11];
    const float* v2   = (const float*)d_in[12];
    float* out = (float*)d_out;

    cudaFuncSetAttribute(tc_mlp, cudaFuncAttributeMaxDynamicSharedMemorySize, SMEM_TOTAL);

    int prep_total = (CH1 + CH2) * 256 * 64;     // 212992
    prep_w<<<(prep_total + 255) / 256, 256>>>(w1, g1, b1, m1, v1,
                                              w2, g2, b2, m2, v2);
    transpose_feat<<<dim3(Nc / 32, CIN / 32, Bc), dim3(32, 8)>>>(feat);
    cylinder_query<<<(Bc * Nc) / 4, 128>>>(xyz, rot);
    tc_mlp<<<Bc * Nc / 4, NTHR, SMEM_TOTAL>>>(out);
}

// round 8
// speedup vs baseline: 1.1395x; 1.1395x over previous
#include <cuda_runtime.h>
#include <cuda_fp16.h>
#include <cstdint>

// ---------------------------------------------------------------------------
// CloudCrop via mma.sync fp16 single-product. R8: K=128 chunks (6 pipeline
// rounds total), rel handled as fp32 FMA in the layer-1 epilogue (no 9th
// chunk). One CTA = 4 points (M=128), N=256, 256 thr, 8 warps, 64x64 tiles.
// ---------------------------------------------------------------------------

#define Bc 4
#define Nc 1024
#define NS 32
#define CIN 512
#define C0 515
#define RADIUSf 0.05f
#define HMINf (-0.02f)
#define HMAXf 0.04f

#define KROWB 272             // A/W tile row bytes (128 fp16 + 16B pad)
#define CH1 4                 // layer-1 chunks of K=128 (features K=512 exactly)
#define CH2 2                 // layer-2 chunks of K=128 (K=256)
#define A2ROWB 528            // y1 row bytes (256 fp16 + 16B pad)
#define A1BUF 34816           // 128 rows * 272B
#define WBUF  69632           // 256 rows * 272B

// smem offsets (dynamic)
#define SM_A2    0            // 128 x 528 = 67584
#define SM_A1    0            // 2 x 34816 (overlays A2; dead until L1 epilogue)
#define SM_W     69632        // 2 x 69632
#define SM_WR    208896       // w1rel+bias1 [256][4] f32 = 4096
#define SM_B2    212992       // bias2 [256] f32 = 1024
#define SM_REL   214016       // rel [128][4] f32 = 2048
#define SM_LIDX  216064       // 128 ints
#define SMEM_TOTAL 216576

// __device__ scratch (allocation-free), 16B-aligned
__device__ __align__(16) unsigned short d_fh[Bc * Nc * CIN];    // feat fp16 [b][n][c]
__device__ __align__(16) int            d_idx[Bc * Nc * NS];
__device__ __align__(16) float          d_rel[Bc * Nc * NS * 3];
__device__ __align__(16) unsigned short d_w1[CH1 * 256 * 128];  // [t][o][128] fp16
__device__ __align__(16) unsigned short d_w2[CH2 * 256 * 128];
__device__ __align__(16) float          d_wr4[256 * 4];         // {wr0,wr1,wr2,bias1}
__device__ __align__(16) float          d_bias2[256];

__device__ __forceinline__ uint32_t s2u(const void* p) {
    uint32_t a;
    asm("{ .reg .u64 t; cvta.to.shared.u64 t, %1; cvt.u32.u64 %0, t; }" : "=r"(a) : "l"(p));
    return a;
}
__device__ __forceinline__ void cpa16(uint32_t dst, const void* src) {
    asm volatile("cp.async.cg.shared.global [%0], [%1], 16;" :: "r"(dst), "l"(src));
}
#define CP_COMMIT()  asm volatile("cp.async.commit_group;" ::: "memory")
#define CP_WAIT0()   asm volatile("cp.async.wait_group 0;" ::: "memory")

__device__ __forceinline__ void ldsm4(uint32_t& r0, uint32_t& r1, uint32_t& r2, uint32_t& r3,
                                      uint32_t addr) {
    asm volatile("ldmatrix.sync.aligned.m8n8.x4.shared.b16 {%0,%1,%2,%3}, [%4];"
                 : "=r"(r0), "=r"(r1), "=r"(r2), "=r"(r3) : "r"(addr));
}
#define MMA(d, A, b0r, b1r) \
    asm volatile("mma.sync.aligned.m16n8k16.row.col.f32.f16.f16.f32 " \
                 "{%0,%1,%2,%3},{%4,%5,%6,%7},{%8,%9},{%0,%1,%2,%3};" \
                 : "+f"((d).x), "+f"((d).y), "+f"((d).z), "+f"((d).w) \
                 : "r"((A)[0]), "r"((A)[1]), "r"((A)[2]), "r"((A)[3]), \
                   "r"(b0r), "r"(b1r))

// One k16 step for a 64x64 warp tile: 4 A-ldsm + 4 B-ldsm, 32 HMMA
template<int AROW>
__device__ __forceinline__ void gemm_kstep(float4 (&acc)[4][8], uint32_t a, uint32_t wb)
{
    uint32_t Ax[4][4], Bf[4][4];
    #pragma unroll
    for (int mt = 0; mt < 4; mt++)
        ldsm4(Ax[mt][0], Ax[mt][1], Ax[mt][2], Ax[mt][3], a + mt * 16 * AROW);
    #pragma unroll
    for (int p = 0; p < 4; p++)
        ldsm4(Bf[p][0], Bf[p][1], Bf[p][2], Bf[p][3], wb + p * 16 * KROWB);
    #pragma unroll
    for (int mt = 0; mt < 4; mt++) {
        #pragma unroll
        for (int p = 0; p < 4; p++) {
            MMA(acc[mt][2*p],   Ax[mt], Bf[p][0], Bf[p][1]);
            MMA(acc[mt][2*p+1], Ax[mt], Bf[p][2], Bf[p][3]);
        }
    }
}

// ---------------------------------------------------------------------------
// Prep: fold BN into weights -> fp16 rn, chunked [t][o][128]; w1 cols 0..2
// (rel) + bias1 go to d_wr4 as fp32.
// ---------------------------------------------------------------------------
__global__ void prep_w(const float* __restrict__ w1,
                       const float* __restrict__ g1, const float* __restrict__ b1,
                       const float* __restrict__ m1, const float* __restrict__ v1,
                       const float* __restrict__ w2,
                       const float* __restrict__ g2, const float* __restrict__ b2,
                       const float* __restrict__ m2, const float* __restrict__ v2)
{
    int i = blockIdx.x * blockDim.x + threadIdx.x;
    const int W1E = CH1 * 256 * 128;  // 131072
    const int W2E = CH2 * 256 * 128;  // 65536
    if (i < W1E) {
        int t = i >> 15, rem = i & 32767, o = rem >> 7, k = rem & 127;
        int c = t * 128 + k;          // 0..511 = feature channel
        float s = g1[o] * rsqrtf(v1[o] + 1e-5f);
        d_w1[i] = __half_as_ushort(__float2half_rn(w1[o * C0 + c + 3] * s));
    }
    int j = i - W1E;
    if (j >= 0 && j < W2E) {
        int t = j >> 15, rem = j & 32767, o = rem >> 7, k = rem & 127;
        float s = g2[o] * rsqrtf(v2[o] + 1e-5f);
        d_w2[j] = __half_as_ushort(__float2half_rn(w2[o * 256 + t * 128 + k] * s));
    }
    if (i < 256) {
        float s1 = g1[i] * rsqrtf(v1[i] + 1e-5f);
        d_wr4[i * 4 + 0] = w1[i * C0 + 0] * s1;
        d_wr4[i * 4 + 1] = w1[i * C0 + 1] * s1;
        d_wr4[i * 4 + 2] = w1[i * C0 + 2] * s1;
        d_wr4[i * 4 + 3] = b1[i] - m1[i] * s1;
        float s2 = g2[i] * rsqrtf(v2[i] + 1e-5f);
        d_bias2[i] = b2[i] - m2[i] * s2;
    }
}

// Transpose [B,512,N] -> point-major fp16 [B,N,512]
__global__ void transpose_feat(const float* __restrict__ f)
{
    __shared__ float tile[32][33];
    int b  = blockIdx.z;
    int c0 = blockIdx.y * 32;
    int n0 = blockIdx.x * 32;
    int tx = threadIdx.x, ty = threadIdx.y;
    const float* src = f + (size_t)b * CIN * Nc;
    #pragma unroll
    for (int k = 0; k < 32; k += 8)
        tile[ty + k][tx] = src[(c0 + ty + k) * Nc + n0 + tx];
    __syncthreads();
    size_t base = (size_t)b * Nc * CIN;
    #pragma unroll
    for (int k = 0; k < 32; k += 8) {
        float v = tile[tx][ty + k];
        d_fh[base + (size_t)(n0 + ty + k) * CIN + c0 + tx] =
            __half_as_ushort(__float2half_rn(v));
    }
}

__global__ void cylinder_query(const float* __restrict__ xyz,
                               const float* __restrict__ rot)
{
    __shared__ int sidx[4][NS];
    int w    = threadIdx.x >> 5;
    int lane = threadIdx.x & 31;
    int p = blockIdx.x * 4 + w;
    int b = p >> 10, n = p & 1023;

    const float* X = xyz + (size_t)b * Nc * 3;
    float cx = X[n * 3 + 0], cy = X[n * 3 + 1], cz = X[n * 3 + 2];
    const float* R = rot + (size_t)p * 9;
    float r00 = R[0], r01 = R[1], r02 = R[2];
    float r10 = R[3], r11 = R[4], r12 = R[5];
    float r20 = R[6], r21 = R[7], r22 = R[8];
    const float R2 = RADIUSf * RADIUSf;

    int cnt = 0;
    for (int m0 = 0; m0 < Nc; m0 += 32) {
        int m = m0 + lane;
        float dx = X[m * 3 + 0] - cx;
        float dy = X[m * 3 + 1] - cy;
        float dz = X[m * 3 + 2] - cz;
        float xr = r00 * dx + r01 * dy + r02 * dz;
        float yr = r10 * dx + r11 * dy + r12 * dz;
        float zr = r20 * dx + r21 * dy + r22 * dz;
        bool mk = (yr * yr + zr * zr < R2) && (xr > HMINf) && (xr < HMAXf);
        unsigned bal = __ballot_sync(0xffffffffu, mk);
        int pre = __popc(bal & ((1u << lane) - 1u));
        int slot = cnt + pre;
        if (mk && slot < NS) sidx[w][slot] = m;
        cnt += __popc(bal);
        if (cnt >= NS) break;
    }
    __syncwarp();
    int c32 = cnt < NS ? cnt : NS;
    int pad = (cnt > 0) ? sidx[w][0] : 0;
    int j = (lane < c32) ? sidx[w][lane] : pad;

    d_idx[p * NS + lane] = j;
    float dx = X[j * 3 + 0] - cx;
    float dy = X[j * 3 + 1] - cy;
    float dz = X[j * 3 + 2] - cz;
    float inv = 1.0f / RADIUSf;
    d_rel[(p * NS + lane) * 3 + 0] = (dx * r00 + dy * r10 + dz * r20) * inv;
    d_rel[(p * NS + lane) * 3 + 1] = (dx * r01 + dy * r11 + dz * r21) * inv;
    d_rel[(p * NS + lane) * 3 + 2] = (dx * r02 + dy * r12 + dz * r22) * inv;
}

// ---------------------------------------------------------------------------
// Main: one CTA = 4 points (M=128), N=256, 256 threads, 8 warps (2M x 4N),
// warp tile 64x64. K=128 chunk pipeline (4+2 rounds); rel via fp32 FMA in
// the layer-1 epilogue.
// ---------------------------------------------------------------------------
__global__ void __launch_bounds__(256, 1)
tc_mlp(float* __restrict__ out)
{
    extern __shared__ char smem[];
    uint32_t sb = s2u(smem);
    int tid  = threadIdx.x;
    int lane = tid & 31;
    int w    = tid >> 5;
    int mh   = w >> 2;            // m-half (0/1): rows mh*64..
    int nq   = w & 3;             // n-quarter: cols nq*64..
    int blk  = blockIdx.x;
    int bb   = blk >> 8;
    int nbase = (blk & 255) * 4;

    float* wr4s   = (float*)(smem + SM_WR);    // [256][4]
    float* bias2s = (float*)(smem + SM_B2);
    float* rels   = (float*)(smem + SM_REL);   // [128][4]
    int*   lidx   = (int*)(smem + SM_LIDX);

    if (tid < 128) {
        lidx[tid] = d_idx[blk * 128 + tid];
        rels[tid * 4 + 0] = d_rel[(blk * 128 + tid) * 3 + 0];
        rels[tid * 4 + 1] = d_rel[(blk * 128 + tid) * 3 + 1];
        rels[tid * 4 + 2] = d_rel[(blk * 128 + tid) * 3 + 2];
        rels[tid * 4 + 3] = 0.f;
    }
    *(float4*)(wr4s + tid * 4) = *(const float4*)(d_wr4 + tid * 4);
    bias2s[tid] = d_bias2[tid];
    __syncthreads();

    const char* fbh = (const char*)d_fh + (size_t)bb * (Nc * CIN * 2);

    // lane-dependent fragment offsets
    uint32_t a1_off = (uint32_t)((mh * 64 + (lane & 15)) * KROWB + (lane >> 4) * 16);
    uint32_t a2_off = (uint32_t)((mh * 64 + (lane & 15)) * A2ROWB + (lane >> 4) * 16);
    uint32_t w_off  = (uint32_t)((nq * 64 + (lane & 7) + ((lane >> 4) << 3)) * KROWB
                                 + ((lane >> 3) & 1) * 16);

    // ---- prefetch helpers (K=128 chunks) ----
    auto issue1 = [&](int t) {
        int buf = t & 1;
        #pragma unroll
        for (int it = 0; it < 8; it++) {
            int e = tid + it * 256;            // 0..2047 : A tile 128 x 256B
            int r = e >> 4, q = e & 15;
            uint32_t dst = sb + SM_A1 + (uint32_t)(buf * A1BUF + r * KROWB + q * 16);
            const char* srcb = fbh + (size_t)lidx[r] * 1024 + t * 256 + q * 16;
            cpa16(dst, srcb);
        }
        #pragma unroll
        for (int it = 0; it < 16; it++) {
            int e = tid + it * 256;            // 0..4095 : W tile 256 x 256B
            int o = e >> 4, q = e & 15;
            uint32_t dst = sb + SM_W + (uint32_t)(buf * WBUF + o * KROWB + q * 16);
            const char* srcb = (const char*)d_w1 + (size_t)t * 65536 + o * 256 + q * 16;
            cpa16(dst, srcb);
        }
        CP_COMMIT();
    };
    auto issue2 = [&](int t) {
        #pragma unroll
        for (int it = 0; it < 16; it++) {
            int e = tid + it * 256;
            int o = e >> 4, q = e & 15;
            uint32_t dst = sb + SM_W + (uint32_t)((t & 1) * WBUF + o * KROWB + q * 16);
            const char* srcb = (const char*)d_w2 + (size_t)t * 65536 + o * 256 + q * 16;
            cpa16(dst, srcb);
        }
        CP_COMMIT();
    };

    float4 acc[4][8];
    #pragma unroll
    for (int mt = 0; mt < 4; mt++)
        #pragma unroll
        for (int nt = 0; nt < 8; nt++) acc[mt][nt] = make_float4(0.f, 0.f, 0.f, 0.f);

    // ================= layer 1: 4 rounds of K=128 =================
    issue1(0);
    for (int t = 0; t < CH1; t++) {
        int buf = t & 1;
        CP_WAIT0();
        __syncthreads();
        if (t + 1 < CH1) issue1(t + 1);
        uint32_t a  = sb + SM_A1 + (uint32_t)(buf * A1BUF) + a1_off;
        uint32_t wb = sb + SM_W  + (uint32_t)(buf * WBUF)  + w_off;
        #pragma unroll
        for (int kk = 0; kk < 8; kk++)
            gemm_kstep<KROWB>(acc, a + kk * 32, wb + kk * 32);
    }
    __syncthreads();   // all warps done reading A1/W before A2 overlay writes

    // ---- layer-1 epilogue: + rel·w1rel (fp32) + bias, relu -> fp16 A2 ----
    {
        #pragma unroll
        for (int mt = 0; mt < 4; mt++) {
            int row0 = mh * 64 + mt * 16 + (lane >> 2);
            float4 r0 = *(float4*)(rels + row0 * 4);         // {x,y,z,0}
            float4 r1 = *(float4*)(rels + (row0 + 8) * 4);
            #pragma unroll
            for (int nt = 0; nt < 8; nt++) {
                int col0 = nq * 64 + nt * 8 + (lane & 3) * 2;
                float4 wa = *(float4*)(wr4s + col0 * 4);     // {wr0,wr1,wr2,bias}
                float4 wbv = *(float4*)(wr4s + (col0 + 1) * 4);
                float4 c = acc[mt][nt];
                float y00 = c.x + r0.x*wa.x  + r0.y*wa.y  + r0.z*wa.z  + wa.w;
                float y01 = c.y + r0.x*wbv.x + r0.y*wbv.y + r0.z*wbv.z + wbv.w;
                float y10 = c.z + r1.x*wa.x  + r1.y*wa.y  + r1.z*wa.z  + wa.w;
                float y11 = c.w + r1.x*wbv.x + r1.y*wbv.y + r1.z*wbv.z + wbv.w;
                unsigned short h0 = __half_as_ushort(__float2half_rn(fmaxf(y00, 0.f)));
                unsigned short h1 = __half_as_ushort(__float2half_rn(fmaxf(y01, 0.f)));
                *(uint32_t*)(smem + SM_A2 + row0 * A2ROWB + col0 * 2) = h0 | ((uint32_t)h1 << 16);
                h0 = __half_as_ushort(__float2half_rn(fmaxf(y10, 0.f)));
                h1 = __half_as_ushort(__float2half_rn(fmaxf(y11, 0.f)));
                *(uint32_t*)(smem + SM_A2 + (row0 + 8) * A2ROWB + col0 * 2) = h0 | ((uint32_t)h1 << 16);
            }
        }
    }
    #pragma unroll
    for (int mt = 0; mt < 4; mt++)
        #pragma unroll
        for (int nt = 0; nt < 8; nt++) acc[mt][nt] = make_float4(0.f, 0.f, 0.f, 0.f);
    __syncthreads();

    // ================= layer 2: 2 rounds of K=128 =================
    issue2(0);
    for (int t = 0; t < CH2; t++) {
        int buf = t & 1;
        CP_WAIT0();
        __syncthreads();
        if (t + 1 < CH2) issue2(t + 1);
        uint32_t a  = sb + SM_A2 + a2_off + (uint32_t)(t * 256);
        uint32_t wb = sb + SM_W + (uint32_t)(buf * WBUF) + w_off;
        #pragma unroll
        for (int kk = 0; kk < 8; kk++)
            gemm_kstep<A2ROWB>(acc, a + kk * 32, wb + kk * 32);
    }

    // ---- layer-2 epilogue: maxpool over 32 samples + bias + relu ----
    #pragma unroll
    for (int nt = 0; nt < 8; nt++) {
        float4 c0 = acc[0][nt], c1 = acc[1][nt], c2 = acc[2][nt], c3 = acc[3][nt];
        float p0a = fmaxf(fmaxf(c0.x, c0.z), fmaxf(c1.x, c1.z));   // point mh*2,   col0
        float p0b = fmaxf(fmaxf(c0.y, c0.w), fmaxf(c1.y, c1.w));   //               col0+1
        float p1a = fmaxf(fmaxf(c2.x, c2.z), fmaxf(c3.x, c3.z));   // point mh*2+1, col0
        float p1b = fmaxf(fmaxf(c2.y, c2.w), fmaxf(c3.y, c3.w));
        #pragma unroll
        for (int off = 4; off < 32; off <<= 1) {
            p0a = fmaxf(p0a, __shfl_xor_sync(0xffffffffu, p0a, off));
            p0b = fmaxf(p0b, __shfl_xor_sync(0xffffffffu, p0b, off));
            p1a = fmaxf(p1a, __shfl_xor_sync(0xffffffffu, p1a, off));
            p1b = fmaxf(p1b, __shfl_xor_sync(0xffffffffu, p1b, off));
        }
        if (lane < 4) {
            int col0 = nq * 64 + nt * 8 + lane * 2;
            int n0 = nbase + mh * 2;
            float bA = bias2s[col0], bB = bias2s[col0 + 1];
            out[((size_t)bb * 256 + col0)     * 1024 + n0]     = fmaxf(p0a + bA, 0.f);
            out[((size_t)bb * 256 + col0 + 1) * 1024 + n0]     = fmaxf(p0b + bB, 0.f);
            out[((size_t)bb * 256 + col0)     * 1024 + n0 + 1] = fmaxf(p1a + bA, 0.f);
            out[((size_t)bb * 256 + col0 + 1) * 1024 + n0 + 1] = fmaxf(p1b + bB, 0.f);
        }
    }
}

// ---------------------------------------------------------------------------
extern "C" void kernel_launch(void* const* d_in, const int* in_sizes, int n_in,
                              void* d_out, int out_size)
{
    const float* xyz  = (const float*)d_in[0];
    const float* feat = (const float*)d_in[1];
    const float* rot  = (const float*)d_in[2];
    const float* w1   = (const float*)d_in[3];
    const float* g1   = (const float*)d_in[4];
    const float* b1   = (const float*)d_in[5];
    const float* m1   = (const float*)d_in[6];
    const float* v1   = (const float*)d_in[7];
    const float* w2   = (const float*)d_in[8];
    const float* g2   = (const float*)d_in[9];
    const float* b2   = (const float*)d_in[10];
    const float* m2   = (const float*)d_in[11];
    const float* v2   = (const float*)d_in[12];
    float* out = (float*)d_out;

    cudaFuncSetAttribute(tc_mlp, cudaFuncAttributeMaxDynamicSharedMemorySize, SMEM_TOTAL);

    int prep_total = (CH1 + CH2) * 256 * 128;    // 196608
    prep_w<<<(prep_total + 255) / 256, 256>>>(w1, g1, b1, m1, v1,
                                              w2, g2, b2, m2, v2);
    transpose_feat<<<dim3(Nc / 32, CIN / 32, Bc), dim3(32, 8)>>>(feat);
    cylinder_query<<<(Bc * Nc) / 4, 128>>>(xyz, rot);
    tc_mlp<<<Bc * Nc / 4, 256, SMEM_TOTAL>>>(out);
}

// round 9
// speedup vs baseline: 1.1525x; 1.0114x over previous
#include <cuda_runtime.h>
#include <cuda_fp16.h>
#include <cstdint>

// ---------------------------------------------------------------------------
// CloudCrop via mma.sync fp16 single-product. R9: explicit ldsm double-
// buffering inside each K=128 round (hide LDS latency under MMAs) + W2
// prefetch behind layer-1 compute/epilogue. One CTA = 4 points (M=128),
// N=256, 256 thr, 8 warps, 64x64 tiles.
// ---------------------------------------------------------------------------

#define Bc 4
#define Nc 1024
#define NS 32
#define CIN 512
#define C0 515
#define RADIUSf 0.05f
#define HMINf (-0.02f)
#define HMAXf 0.04f

#define KROWB 272             // A/W tile row bytes (128 fp16 + 16B pad)
#define CH1 4                 // layer-1 chunks of K=128 (features K=512 exactly)
#define CH2 2                 // layer-2 chunks of K=128 (K=256)
#define A2ROWB 528            // y1 row bytes (256 fp16 + 16B pad)
#define A1BUF 34816           // 128 rows * 272B
#define WBUF  69632           // 256 rows * 272B

// smem offsets (dynamic)
#define SM_A2    0            // 128 x 528 = 67584
#define SM_A1    0            // 2 x 34816 (overlays A2; dead until L1 epilogue)
#define SM_W     69632        // 2 x 69632
#define SM_WR    208896       // w1rel+bias1 [256][4] f32 = 4096
#define SM_B2    212992       // bias2 [256] f32 = 1024
#define SM_REL   214016       // rel [128][4] f32 = 2048
#define SM_LIDX  216064       // 128 ints
#define SMEM_TOTAL 216576

// __device__ scratch (allocation-free), 16B-aligned
__device__ __align__(16) unsigned short d_fh[Bc * Nc * CIN];    // feat fp16 [b][n][c]
__device__ __align__(16) int            d_idx[Bc * Nc * NS];
__device__ __align__(16) float          d_rel[Bc * Nc * NS * 3];
__device__ __align__(16) unsigned short d_w1[CH1 * 256 * 128];  // [t][o][128] fp16
__device__ __align__(16) unsigned short d_w2[CH2 * 256 * 128];
__device__ __align__(16) float          d_wr4[256 * 4];         // {wr0,wr1,wr2,bias1}
__device__ __align__(16) float          d_bias2[256];

__device__ __forceinline__ uint32_t s2u(const void* p) {
    uint32_t a;
    asm("{ .reg .u64 t; cvta.to.shared.u64 t, %1; cvt.u32.u64 %0, t; }" : "=r"(a) : "l"(p));
    return a;
}
__device__ __forceinline__ void cpa16(uint32_t dst, const void* src) {
    asm volatile("cp.async.cg.shared.global [%0], [%1], 16;" :: "r"(dst), "l"(src));
}
#define CP_COMMIT()  asm volatile("cp.async.commit_group;" ::: "memory")
#define CP_WAIT0()   asm volatile("cp.async.wait_group 0;" ::: "memory")
#define CP_WAIT1()   asm volatile("cp.async.wait_group 1;" ::: "memory")

__device__ __forceinline__ void ldsm4(uint32_t& r0, uint32_t& r1, uint32_t& r2, uint32_t& r3,
                                      uint32_t addr) {
    asm volatile("ldmatrix.sync.aligned.m8n8.x4.shared.b16 {%0,%1,%2,%3}, [%4];"
                 : "=r"(r0), "=r"(r1), "=r"(r2), "=r"(r3) : "r"(addr));
}
#define MMA(d, A, b0r, b1r) \
    asm volatile("mma.sync.aligned.m16n8k16.row.col.f32.f16.f16.f32 " \
                 "{%0,%1,%2,%3},{%4,%5,%6,%7},{%8,%9},{%0,%1,%2,%3};" \
                 : "+f"((d).x), "+f"((d).y), "+f"((d).z), "+f"((d).w) \
                 : "r"((A)[0]), "r"((A)[1]), "r"((A)[2]), "r"((A)[3]), \
                   "r"(b0r), "r"(b1r))

struct Frags { uint32_t A[4][4]; uint32_t B[4][4]; };

template<int AROW>
__device__ __forceinline__ void load_frags(Frags& f, uint32_t a, uint32_t wb) {
    #pragma unroll
    for (int mt = 0; mt < 4; mt++)
        ldsm4(f.A[mt][0], f.A[mt][1], f.A[mt][2], f.A[mt][3], a + mt * 16 * AROW);
    #pragma unroll
    for (int p = 0; p < 4; p++)
        ldsm4(f.B[p][0], f.B[p][1], f.B[p][2], f.B[p][3], wb + p * 16 * KROWB);
}
__device__ __forceinline__ void mma_frags(float4 (&acc)[4][8], const Frags& f) {
    #pragma unroll
    for (int mt = 0; mt < 4; mt++) {
        #pragma unroll
        for (int p = 0; p < 4; p++) {
            MMA(acc[mt][2*p],   f.A[mt], f.B[p][0], f.B[p][1]);
            MMA(acc[mt][2*p+1], f.A[mt], f.B[p][2], f.B[p][3]);
        }
    }
}

// One K=128 round with fragment double-buffering: ldsm for kk+1 in flight
// while MMAs of kk run on the tensor pipe.
template<int AROW>
__device__ __forceinline__ void gemm_round(float4 (&acc)[4][8], uint32_t a, uint32_t wb) {
    Frags f0, f1;
    load_frags<AROW>(f0, a, wb);
    #pragma unroll
    for (int kk = 0; kk < 8; kk++) {
        Frags& cur = (kk & 1) ? f1 : f0;
        Frags& nxt = (kk & 1) ? f0 : f1;
        if (kk < 7)
            load_frags<AROW>(nxt, a + (kk + 1) * 32, wb + (kk + 1) * 32);
        mma_frags(acc, cur);
    }
}

// ---------------------------------------------------------------------------
// Prep: fold BN into weights -> fp16 rn, chunked [t][o][128]; w1 cols 0..2
// (rel) + bias1 go to d_wr4 as fp32.
// ---------------------------------------------------------------------------
__global__ void prep_w(const float* __restrict__ w1,
                       const float* __restrict__ g1, const float* __restrict__ b1,
                       const float* __restrict__ m1, const float* __restrict__ v1,
                       const float* __restrict__ w2,
                       const float* __restrict__ g2, const float* __restrict__ b2,
                       const float* __restrict__ m2, const float* __restrict__ v2)
{
    int i = blockIdx.x * blockDim.x + threadIdx.x;
    const int W1E = CH1 * 256 * 128;  // 131072
    const int W2E = CH2 * 256 * 128;  // 65536
    if (i < W1E) {
        int t = i >> 15, rem = i & 32767, o = rem >> 7, k = rem & 127;
        int c = t * 128 + k;          // 0..511 = feature channel
        float s = g1[o] * rsqrtf(v1[o] + 1e-5f);
        d_w1[i] = __half_as_ushort(__float2half_rn(w1[o * C0 + c + 3] * s));
    }
    int j = i - W1E;
    if (j >= 0 && j < W2E) {
        int t = j >> 15, rem = j & 32767, o = rem >> 7, k = rem & 127;
        float s = g2[o] * rsqrtf(v2[o] + 1e-5f);
        d_w2[j] = __half_as_ushort(__float2half_rn(w2[o * 256 + t * 128 + k] * s));
    }
    if (i < 256) {
        float s1 = g1[i] * rsqrtf(v1[i] + 1e-5f);
        d_wr4[i * 4 + 0] = w1[i * C0 + 0] * s1;
        d_wr4[i * 4 + 1] = w1[i * C0 + 1] * s1;
        d_wr4[i * 4 + 2] = w1[i * C0 + 2] * s1;
        d_wr4[i * 4 + 3] = b1[i] - m1[i] * s1;
        float s2 = g2[i] * rsqrtf(v2[i] + 1e-5f);
        d_bias2[i] = b2[i] - m2[i] * s2;
    }
}

// Transpose [B,512,N] -> point-major fp16 [B,N,512]
__global__ void transpose_feat(const float* __restrict__ f)
{
    __shared__ float tile[32][33];
    int b  = blockIdx.z;
    int c0 = blockIdx.y * 32;
    int n0 = blockIdx.x * 32;
    int tx = threadIdx.x, ty = threadIdx.y;
    const float* src = f + (size_t)b * CIN * Nc;
    #pragma unroll
    for (int k = 0; k < 32; k += 8)
        tile[ty + k][tx] = src[(c0 + ty + k) * Nc + n0 + tx];
    __syncthreads();
    size_t base = (size_t)b * Nc * CIN;
    #pragma unroll
    for (int k = 0; k < 32; k += 8) {
        float v = tile[tx][ty + k];
        d_fh[base + (size_t)(n0 + ty + k) * CIN + c0 + tx] =
            __half_as_ushort(__float2half_rn(v));
    }
}

__global__ void cylinder_query(const float* __restrict__ xyz,
                               const float* __restrict__ rot)
{
    __shared__ int sidx[4][NS];
    int w    = threadIdx.x >> 5;
    int lane = threadIdx.x & 31;
    int p = blockIdx.x * 4 + w;
    int b = p >> 10, n = p & 1023;

    const float* X = xyz + (size_t)b * Nc * 3;
    float cx = X[n * 3 + 0], cy = X[n * 3 + 1], cz = X[n * 3 + 2];
    const float* R = rot + (size_t)p * 9;
    float r00 = R[0], r01 = R[1], r02 = R[2];
    float r10 = R[3], r11 = R[4], r12 = R[5];
    float r20 = R[6], r21 = R[7], r22 = R[8];
    const float R2 = RADIUSf * RADIUSf;

    int cnt = 0;
    for (int m0 = 0; m0 < Nc; m0 += 32) {
        int m = m0 + lane;
        float dx = X[m * 3 + 0] - cx;
        float dy = X[m * 3 + 1] - cy;
        float dz = X[m * 3 + 2] - cz;
        float xr = r00 * dx + r01 * dy + r02 * dz;
        float yr = r10 * dx + r11 * dy + r12 * dz;
        float zr = r20 * dx + r21 * dy + r22 * dz;
        bool mk = (yr * yr + zr * zr < R2) && (xr > HMINf) && (xr < HMAXf);
        unsigned bal = __ballot_sync(0xffffffffu, mk);
        int pre = __popc(bal & ((1u << lane) - 1u));
        int slot = cnt + pre;
        if (mk && slot < NS) sidx[w][slot] = m;
        cnt += __popc(bal);
        if (cnt >= NS) break;
    }
    __syncwarp();
    int c32 = cnt < NS ? cnt : NS;
    int pad = (cnt > 0) ? sidx[w][0] : 0;
    int j = (lane < c32) ? sidx[w][lane] : pad;

    d_idx[p * NS + lane] = j;
    float dx = X[j * 3 + 0] - cx;
    float dy = X[j * 3 + 1] - cy;
    float dz = X[j * 3 + 2] - cz;
    float inv = 1.0f / RADIUSf;
    d_rel[(p * NS + lane) * 3 + 0] = (dx * r00 + dy * r10 + dz * r20) * inv;
    d_rel[(p * NS + lane) * 3 + 1] = (dx * r01 + dy * r11 + dz * r21) * inv;
    d_rel[(p * NS + lane) * 3 + 2] = (dx * r02 + dy * r12 + dz * r22) * inv;
}

// ---------------------------------------------------------------------------
// Main: one CTA = 4 points (M=128), N=256, 256 threads, 8 warps (2M x 4N),
// warp tile 64x64. K=128 chunk pipeline; W2 prefetched behind layer 1.
// ---------------------------------------------------------------------------
__global__ void __launch_bounds__(256, 1)
tc_mlp(float* __restrict__ out)
{
    extern __shared__ char smem[];
    uint32_t sb = s2u(smem);
    int tid  = threadIdx.x;
    int lane = tid & 31;
    int w    = tid >> 5;
    int mh   = w >> 2;            // m-half (0/1): rows mh*64..
    int nq   = w & 3;             // n-quarter: cols nq*64..
    int blk  = blockIdx.x;
    int bb   = blk >> 8;
    int nbase = (blk & 255) * 4;

    float* wr4s   = (float*)(smem + SM_WR);    // [256][4]
    float* bias2s = (float*)(smem + SM_B2);
    float* rels   = (float*)(smem + SM_REL);   // [128][4]
    int*   lidx   = (int*)(smem + SM_LIDX);

    if (tid < 128) {
        lidx[tid] = d_idx[blk * 128 + tid];
        rels[tid * 4 + 0] = d_rel[(blk * 128 + tid) * 3 + 0];
        rels[tid * 4 + 1] = d_rel[(blk * 128 + tid) * 3 + 1];
        rels[tid * 4 + 2] = d_rel[(blk * 128 + tid) * 3 + 2];
        rels[tid * 4 + 3] = 0.f;
    }
    *(float4*)(wr4s + tid * 4) = *(const float4*)(d_wr4 + tid * 4);
    bias2s[tid] = d_bias2[tid];
    __syncthreads();

    const char* fbh = (const char*)d_fh + (size_t)bb * (Nc * CIN * 2);

    // lane-dependent fragment offsets
    uint32_t a1_off = (uint32_t)((mh * 64 + (lane & 15)) * KROWB + (lane >> 4) * 16);
    uint32_t a2_off = (uint32_t)((mh * 64 + (lane & 15)) * A2ROWB + (lane >> 4) * 16);
    uint32_t w_off  = (uint32_t)((nq * 64 + (lane & 7) + ((lane >> 4) << 3)) * KROWB
                                 + ((lane >> 3) & 1) * 16);

    // ---- prefetch helpers (K=128 chunks) ----
    auto issue1 = [&](int t) {
        int buf = t & 1;
        #pragma unroll
        for (int it = 0; it < 8; it++) {
            int e = tid + it * 256;            // 0..2047 : A tile 128 x 256B
            int r = e >> 4, q = e & 15;
            uint32_t dst = sb + SM_A1 + (uint32_t)(buf * A1BUF + r * KROWB + q * 16);
            const char* srcb = fbh + (size_t)lidx[r] * 1024 + t * 256 + q * 16;
            cpa16(dst, srcb);
        }
        #pragma unroll
        for (int it = 0; it < 16; it++) {
            int e = tid + it * 256;            // 0..4095 : W tile 256 x 256B
            int o = e >> 4, q = e & 15;
            uint32_t dst = sb + SM_W + (uint32_t)(buf * WBUF + o * KROWB + q * 16);
            const char* srcb = (const char*)d_w1 + (size_t)t * 65536 + o * 256 + q * 16;
            cpa16(dst, srcb);
        }
        CP_COMMIT();
    };
    auto issue2 = [&](int t) {
        #pragma unroll
        for (int it = 0; it < 16; it++) {
            int e = tid + it * 256;
            int o = e >> 4, q = e & 15;
            uint32_t dst = sb + SM_W + (uint32_t)((t & 1) * WBUF + o * KROWB + q * 16);
            const char* srcb = (const char*)d_w2 + (size_t)t * 65536 + o * 256 + q * 16;
            cpa16(dst, srcb);
        }
        CP_COMMIT();
    };

    float4 acc[4][8];
    #pragma unroll
    for (int mt = 0; mt < 4; mt++)
        #pragma unroll
        for (int nt = 0; nt < 8; nt++) acc[mt][nt] = make_float4(0.f, 0.f, 0.f, 0.f);

    // ================= layer 1: 4 rounds of K=128 =================
    issue1(0);
    for (int t = 0; t < CH1; t++) {
        int buf = t & 1;
        CP_WAIT0();
        __syncthreads();
        if (t + 1 < CH1) issue1(t + 1);
        else             issue2(0);           // W2 chunk0 -> W buf0 (free after sync)
        uint32_t a  = sb + SM_A1 + (uint32_t)(buf * A1BUF) + a1_off;
        uint32_t wb = sb + SM_W  + (uint32_t)(buf * WBUF)  + w_off;
        gemm_round<KROWB>(acc, a, wb);
    }
    __syncthreads();   // all warps done reading A1/W buf1 before overwrites
    issue2(1);         // W2 chunk1 -> W buf1; overlaps the epilogue below

    // ---- layer-1 epilogue: + rel·w1rel (fp32) + bias, relu -> fp16 A2 ----
    {
        #pragma unroll
        for (int mt = 0; mt < 4; mt++) {
            int row0 = mh * 64 + mt * 16 + (lane >> 2);
            float4 r0 = *(float4*)(rels + row0 * 4);         // {x,y,z,0}
            float4 r1 = *(float4*)(rels + (row0 + 8) * 4);
            #pragma unroll
            for (int nt = 0; nt < 8; nt++) {
                int col0 = nq * 64 + nt * 8 + (lane & 3) * 2;
                float4 wa = *(float4*)(wr4s + col0 * 4);     // {wr0,wr1,wr2,bias}
                float4 wbv = *(float4*)(wr4s + (col0 + 1) * 4);
                float4 c = acc[mt][nt];
                float y00 = c.x + r0.x*wa.x  + r0.y*wa.y  + r0.z*wa.z  + wa.w;
                float y01 = c.y + r0.x*wbv.x + r0.y*wbv.y + r0.z*wbv.z + wbv.w;
                float y10 = c.z + r1.x*wa.x  + r1.y*wa.y  + r1.z*wa.z  + wa.w;
                float y11 = c.w + r1.x*wbv.x + r1.y*wbv.y + r1.z*wbv.z + wbv.w;
                unsigned short h0 = __half_as_ushort(__float2half_rn(fmaxf(y00, 0.f)));
                unsigned short h1 = __half_as_ushort(__float2half_rn(fmaxf(y01, 0.f)));
                *(uint32_t*)(smem + SM_A2 + row0 * A2ROWB + col0 * 2) = h0 | ((uint32_t)h1 << 16);
                h0 = __half_as_ushort(__float2half_rn(fmaxf(y10, 0.f)));
                h1 = __half_as_ushort(__float2half_rn(fmaxf(y11, 0.f)));
                *(uint32_t*)(smem + SM_A2 + (row0 + 8) * A2ROWB + col0 * 2) = h0 | ((uint32_t)h1 << 16);
            }
        }
    }
    #pragma unroll
    for (int mt = 0; mt < 4; mt++)
        #pragma unroll
        for (int nt = 0; nt < 8; nt++) acc[mt][nt] = make_float4(0.f, 0.f, 0.f, 0.f);
    __syncthreads();

    // ================= layer 2: 2 rounds of K=128 (W2 already in flight) ====
    for (int t = 0; t < CH2; t++) {
        if (t == 0) CP_WAIT1();   // W2c0 done (W2c1 may still be pending)
        else        CP_WAIT0();   // W2c1 done
        __syncthreads();
        uint32_t a  = sb + SM_A2 + a2_off + (uint32_t)(t * 256);
        uint32_t wb = sb + SM_W + (uint32_t)((t & 1) * WBUF) + w_off;
        gemm_round<A2ROWB>(acc, a, wb);
    }

    // ---- layer-2 epilogue: maxpool over 32 samples + bias + relu ----
    #pragma unroll
    for (int nt = 0; nt < 8; nt++) {
        float4 c0 = acc[0][nt], c1 = acc[1][nt], c2 = acc[2][nt], c3 = acc[3][nt];
        float p0a = fmaxf(fmaxf(c0.x, c0.z), fmaxf(c1.x, c1.z));   // point mh*2,   col0
        float p0b = fmaxf(fmaxf(c0.y, c0.w), fmaxf(c1.y, c1.w));   //               col0+1
        float p1a = fmaxf(fmaxf(c2.x, c2.z), fmaxf(c3.x, c3.z));   // point mh*2+1, col0
        float p1b = fmaxf(fmaxf(c2.y, c2.w), fmaxf(c3.y, c3.w));
        #pragma unroll
        for (int off = 4; off < 32; off <<= 1) {
            p0a = fmaxf(p0a, __shfl_xor_sync(0xffffffffu, p0a, off));
            p0b = fmaxf(p0b, __shfl_xor_sync(0xffffffffu, p0b, off));
            p1a = fmaxf(p1a, __shfl_xor_sync(0xffffffffu, p1a, off));
            p1b = fmaxf(p1b, __shfl_xor_sync(0xffffffffu, p1b, off));
        }
        if (lane < 4) {
            int col0 = nq * 64 + nt * 8 + lane * 2;
            int n0 = nbase + mh * 2;
            float bA = bias2s[col0], bB = bias2s[col0 + 1];
            out[((size_t)bb * 256 + col0)     * 1024 + n0]     = fmaxf(p0a + bA, 0.f);
            out[((size_t)bb * 256 + col0 + 1) * 1024 + n0]     = fmaxf(p0b + bB, 0.f);
            out[((size_t)bb * 256 + col0)     * 1024 + n0 + 1] = fmaxf(p1a + bA, 0.f);
            out[((size_t)bb * 256 + col0 + 1) * 1024 + n0 + 1] = fmaxf(p1b + bB, 0.f);
        }
    }
}

// ---------------------------------------------------------------------------
extern "C" void kernel_launch(void* const* d_in, const int* in_sizes, int n_in,
                              void* d_out, int out_size)
{
    const float* xyz  = (const float*)d_in[0];
    const float* feat = (const float*)d_in[1];
    const float* rot  = (const float*)d_in[2];
    const float* w1   = (const float*)d_in[3];
    const float* g1   = (const float*)d_in[4];
    const float* b1   = (const float*)d_in[5];
    const float* m1   = (const float*)d_in[6];
    const float* v1   = (const float*)d_in[7];
    const float* w2   = (const float*)d_in[8];
    const float* g2   = (const float*)d_in[9];
    const float* b2   = (const float*)d_in[10];
    const float* m2   = (const float*)d_in[11];
    const float* v2   = (const float*)d_in[12];
    float* out = (float*)d_out;

    cudaFuncSetAttribute(tc_mlp, cudaFuncAttributeMaxDynamicSharedMemorySize, SMEM_TOTAL);

    int prep_total = (CH1 + CH2) * 256 * 128;    // 196608
    prep_w<<<(prep_total + 255) / 256, 256>>>(w1, g1, b1, m1, v1,
                                              w2, g2, b2, m2, v2);
    transpose_feat<<<dim3(Nc / 32, CIN / 32, Bc), dim3(32, 8)>>>(feat);
    cylinder_query<<<(Bc * Nc) / 4, 128>>>(xyz, rot);
    tc_mlp<<<Bc * Nc / 4, 256, SMEM_TOTAL>>>(out);
}

// round 11
// speedup vs baseline: 1.7665x; 1.5328x over previous
#include <cuda_runtime.h>
#include <cuda_fp16.h>
#include <cstdint>

// ---------------------------------------------------------------------------
// CloudCrop R11 (= R10 resubmit after infra failure): factor layer 1 through
// the gather.
//   F = W1f·feat computed ONCE per distinct point (4096 cols) by f_gemm;
//   main kernel: gather F by idx + rank-3 rel update + bias + relu -> GEMM2
//   -> maxpool. Deletes 2/3 of all tensor work vs R9.
// ---------------------------------------------------------------------------

#define Bc 4
#define Nc 1024
#define NS 32
#define CIN 512
#define C0 515
#define RADIUSf 0.05f
#define HMINf (-0.02f)
#define HMAXf 0.04f

#define KROWB 272             // f_gemm A/W tile row bytes (128 fp16 + 16B pad)
#define CH1 4                 // f_gemm K chunks (K=512)
#define A2ROWB 528            // A2 / y1 row bytes (256 fp16 + 16B pad)
#define A1BUF 34816           // 128 rows * 272B
#define WBUF  69632           // 256 rows * 272B

// f_gemm smem: A1 2x34816 @0, W 2x69632 @69632 -> 208896
#define FG_A1    0
#define FG_W     69632
#define FG_TOTAL 208896

// main smem
#define SM_A2    0            // 128 x 528 = 67584
#define SM_W     67584        // 2 x 69632 -> ends 206848
#define SM_WR    206848       // w1rel+bias1 [256][4] f32 = 4096
#define SM_B2    210944       // bias2 f32 = 1024
#define SM_REL   211968       // rel [128][4] f32 = 2048
#define SM_LIDX  214016       // 128 ints = 512
#define SM_TOTAL 214528

// __device__ scratch (allocation-free), 16B-aligned
__device__ __align__(16) unsigned short d_fh[Bc * Nc * CIN];    // feat fp16 [p][c]
__device__ __align__(16) unsigned short d_F[Bc * Nc * 256];     // W1f·feat fp16 [p][o]
__device__ __align__(16) int            d_idx[Bc * Nc * NS];
__device__ __align__(16) float          d_rel[Bc * Nc * NS * 3];
__device__ __align__(16) unsigned short d_w1[CH1 * 256 * 128];  // [t][o][128] fp16
__device__ __align__(16) unsigned short d_w2[2 * 256 * 128];
__device__ __align__(16) float          d_wr4[256 * 4];         // {wr0,wr1,wr2,bias1}
__device__ __align__(16) float          d_bias2[256];

__device__ __forceinline__ uint32_t s2u(const void* p) {
    uint32_t a;
    asm("{ .reg .u64 t; cvta.to.shared.u64 t, %1; cvt.u32.u64 %0, t; }" : "=r"(a) : "l"(p));
    return a;
}
__device__ __forceinline__ void cpa16(uint32_t dst, const void* src) {
    asm volatile("cp.async.cg.shared.global [%0], [%1], 16;" :: "r"(dst), "l"(src));
}
#define CP_COMMIT()  asm volatile("cp.async.commit_group;" ::: "memory")
#define CP_WAITG(n)  asm volatile("cp.async.wait_group %0;" :: "n"(n) : "memory")

__device__ __forceinline__ void ldsm4(uint32_t& r0, uint32_t& r1, uint32_t& r2, uint32_t& r3,
                                      uint32_t addr) {
    asm volatile("ldmatrix.sync.aligned.m8n8.x4.shared.b16 {%0,%1,%2,%3}, [%4];"
                 : "=r"(r0), "=r"(r1), "=r"(r2), "=r"(r3) : "r"(addr));
}
#define MMA(d, A, b0r, b1r) \
    asm volatile("mma.sync.aligned.m16n8k16.row.col.f32.f16.f16.f32 " \
                 "{%0,%1,%2,%3},{%4,%5,%6,%7},{%8,%9},{%0,%1,%2,%3};" \
                 : "+f"((d).x), "+f"((d).y), "+f"((d).z), "+f"((d).w) \
                 : "r"((A)[0]), "r"((A)[1]), "r"((A)[2]), "r"((A)[3]), \
                   "r"(b0r), "r"(b1r))

// One K=128 round for a 64x64 warp tile (8 ksteps x 32 HMMA)
template<int AROW>
__device__ __forceinline__ void gemm_round(float4 (&acc)[4][8], uint32_t a, uint32_t wb)
{
    #pragma unroll
    for (int kk = 0; kk < 8; kk++) {
        uint32_t Ax[4][4], Bf[4][4];
        uint32_t ak = a + kk * 32, wk = wb + kk * 32;
        #pragma unroll
        for (int mt = 0; mt < 4; mt++)
            ldsm4(Ax[mt][0], Ax[mt][1], Ax[mt][2], Ax[mt][3], ak + mt * 16 * AROW);
        #pragma unroll
        for (int p = 0; p < 4; p++)
            ldsm4(Bf[p][0], Bf[p][1], Bf[p][2], Bf[p][3], wk + p * 16 * KROWB);
        #pragma unroll
        for (int mt = 0; mt < 4; mt++) {
            #pragma unroll
            for (int p = 0; p < 4; p++) {
                MMA(acc[mt][2*p],   Ax[mt], Bf[p][0], Bf[p][1]);
                MMA(acc[mt][2*p+1], Ax[mt], Bf[p][2], Bf[p][3]);
            }
        }
    }
}

// ---------------------------------------------------------------------------
// Prep: fold BN -> fp16 weights; rel cols + bias1 -> fp32 d_wr4.
// ---------------------------------------------------------------------------
__global__ void prep_w(const float* __restrict__ w1,
                       const float* __restrict__ g1, const float* __restrict__ b1,
                       const float* __restrict__ m1, const float* __restrict__ v1,
                       const float* __restrict__ w2,
                       const float* __restrict__ g2, const float* __restrict__ b2,
                       const float* __restrict__ m2, const float* __restrict__ v2)
{
    int i = blockIdx.x * blockDim.x + threadIdx.x;
    const int W1E = CH1 * 256 * 128;  // 131072
    const int W2E = 2 * 256 * 128;    // 65536
    if (i < W1E) {
        int t = i >> 15, rem = i & 32767, o = rem >> 7, k = rem & 127;
        int c = t * 128 + k;
        float s = g1[o] * rsqrtf(v1[o] + 1e-5f);
        d_w1[i] = __half_as_ushort(__float2half_rn(w1[o * C0 + c + 3] * s));
    }
    int j = i - W1E;
    if (j >= 0 && j < W2E) {
        int t = j >> 15, rem = j & 32767, o = rem >> 7, k = rem & 127;
        float s = g2[o] * rsqrtf(v2[o] + 1e-5f);
        d_w2[j] = __half_as_ushort(__float2half_rn(w2[o * 256 + t * 128 + k] * s));
    }
    if (i < 256) {
        float s1 = g1[i] * rsqrtf(v1[i] + 1e-5f);
        d_wr4[i * 4 + 0] = w1[i * C0 + 0] * s1;
        d_wr4[i * 4 + 1] = w1[i * C0 + 1] * s1;
        d_wr4[i * 4 + 2] = w1[i * C0 + 2] * s1;
        d_wr4[i * 4 + 3] = b1[i] - m1[i] * s1;
        float s2 = g2[i] * rsqrtf(v2[i] + 1e-5f);
        d_bias2[i] = b2[i] - m2[i] * s2;
    }
}

// Transpose [B,512,N] -> point-major fp16 [p][512]
__global__ void transpose_feat(const float* __restrict__ f)
{
    __shared__ float tile[32][33];
    int b  = blockIdx.z;
    int c0 = blockIdx.y * 32;
    int n0 = blockIdx.x * 32;
    int tx = threadIdx.x, ty = threadIdx.y;
    const float* src = f + (size_t)b * CIN * Nc;
    #pragma unroll
    for (int k = 0; k < 32; k += 8)
        tile[ty + k][tx] = src[(c0 + ty + k) * Nc + n0 + tx];
    __syncthreads();
    size_t base = (size_t)b * Nc * CIN;
    #pragma unroll
    for (int k = 0; k < 32; k += 8) {
        float v = tile[tx][ty + k];
        d_fh[base + (size_t)(n0 + ty + k) * CIN + c0 + tx] =
            __half_as_ushort(__float2half_rn(v));
    }
}

__global__ void cylinder_query(const float* __restrict__ xyz,
                               const float* __restrict__ rot)
{
    __shared__ int sidx[4][NS];
    int w    = threadIdx.x >> 5;
    int lane = threadIdx.x & 31;
    int p = blockIdx.x * 4 + w;
    int b = p >> 10, n = p & 1023;

    const float* X = xyz + (size_t)b * Nc * 3;
    float cx = X[n * 3 + 0], cy = X[n * 3 + 1], cz = X[n * 3 + 2];
    const float* R = rot + (size_t)p * 9;
    float r00 = R[0], r01 = R[1], r02 = R[2];
    float r10 = R[3], r11 = R[4], r12 = R[5];
    float r20 = R[6], r21 = R[7], r22 = R[8];
    const float R2 = RADIUSf * RADIUSf;

    int cnt = 0;
    for (int m0 = 0; m0 < Nc; m0 += 32) {
        int m = m0 + lane;
        float dx = X[m * 3 + 0] - cx;
        float dy = X[m * 3 + 1] - cy;
        float dz = X[m * 3 + 2] - cz;
        float xr = r00 * dx + r01 * dy + r02 * dz;
        float yr = r10 * dx + r11 * dy + r12 * dz;
        float zr = r20 * dx + r21 * dy + r22 * dz;
        bool mk = (yr * yr + zr * zr < R2) && (xr > HMINf) && (xr < HMAXf);
        unsigned bal = __ballot_sync(0xffffffffu, mk);
        int pre = __popc(bal & ((1u << lane) - 1u));
        int slot = cnt + pre;
        if (mk && slot < NS) sidx[w][slot] = m;
        cnt += __popc(bal);
        if (cnt >= NS) break;
    }
    __syncwarp();
    int c32 = cnt < NS ? cnt : NS;
    int pad = (cnt > 0) ? sidx[w][0] : 0;
    int j = (lane < c32) ? sidx[w][lane] : pad;

    d_idx[p * NS + lane] = j;
    float dx = X[j * 3 + 0] - cx;
    float dy = X[j * 3 + 1] - cy;
    float dz = X[j * 3 + 2] - cz;
    float inv = 1.0f / RADIUSf;
    d_rel[(p * NS + lane) * 3 + 0] = (dx * r00 + dy * r10 + dz * r20) * inv;
    d_rel[(p * NS + lane) * 3 + 1] = (dx * r01 + dy * r11 + dz * r21) * inv;
    d_rel[(p * NS + lane) * 3 + 2] = (dx * r02 + dy * r12 + dz * r22) * inv;
}

// ---------------------------------------------------------------------------
// f_gemm: F[p][o] = sum_c feat[p][c] * W1f[o][c]  (raw, no bias/relu).
// 32 CTAs x (M=128 points, N=256, K=512). R8 layer-1 machinery, no gather.
// ---------------------------------------------------------------------------
__global__ void __launch_bounds__(256, 1)
f_gemm()
{
    extern __shared__ char smem[];
    uint32_t sb = s2u(smem);
    int tid  = threadIdx.x;
    int lane = tid & 31;
    int w    = tid >> 5;
    int mh   = w >> 2;
    int nq   = w & 3;
    int p0   = blockIdx.x * 128;

    uint32_t a1_off = (uint32_t)((mh * 64 + (lane & 15)) * KROWB + (lane >> 4) * 16);
    uint32_t w_off  = (uint32_t)((nq * 64 + (lane & 7) + ((lane >> 4) << 3)) * KROWB
                                 + ((lane >> 3) & 1) * 16);

    auto issue = [&](int t) {
        int buf = t & 1;
        #pragma unroll
        for (int it = 0; it < 8; it++) {
            int e = tid + it * 256;            // A: 128 rows x 256B
            int r = e >> 4, q = e & 15;
            uint32_t dst = sb + FG_A1 + (uint32_t)(buf * A1BUF + r * KROWB + q * 16);
            const char* srcb = (const char*)d_fh + (size_t)(p0 + r) * 1024 + t * 256 + q * 16;
            cpa16(dst, srcb);
        }
        #pragma unroll
        for (int it = 0; it < 16; it++) {
            int e = tid + it * 256;            // W: 256 rows x 256B
            int o = e >> 4, q = e & 15;
            uint32_t dst = sb + FG_W + (uint32_t)(buf * WBUF + o * KROWB + q * 16);
            const char* srcb = (const char*)d_w1 + (size_t)t * 65536 + o * 256 + q * 16;
            cpa16(dst, srcb);
        }
        CP_COMMIT();
    };

    float4 acc[4][8];
    #pragma unroll
    for (int mt = 0; mt < 4; mt++)
        #pragma unroll
        for (int nt = 0; nt < 8; nt++) acc[mt][nt] = make_float4(0.f, 0.f, 0.f, 0.f);

    issue(0);
    for (int t = 0; t < CH1; t++) {
        int buf = t & 1;
        CP_WAITG(0);
        __syncthreads();
        if (t + 1 < CH1) issue(t + 1);
        gemm_round<KROWB>(acc,
            sb + FG_A1 + (uint32_t)(buf * A1BUF) + a1_off,
            sb + FG_W  + (uint32_t)(buf * WBUF)  + w_off);
    }

    // write F fp16 (raw accumulators)
    #pragma unroll
    for (int mt = 0; mt < 4; mt++) {
        int row0 = mh * 64 + mt * 16 + (lane >> 2);
        #pragma unroll
        for (int nt = 0; nt < 8; nt++) {
            int col0 = nq * 64 + nt * 8 + (lane & 3) * 2;
            float4 c = acc[mt][nt];
            uint32_t u0 = __half_as_ushort(__float2half_rn(c.x))
                        | ((uint32_t)__half_as_ushort(__float2half_rn(c.y)) << 16);
            uint32_t u1 = __half_as_ushort(__float2half_rn(c.z))
                        | ((uint32_t)__half_as_ushort(__float2half_rn(c.w)) << 16);
            *(uint32_t*)(d_F + (size_t)(p0 + row0) * 256 + col0)       = u0;
            *(uint32_t*)(d_F + (size_t)(p0 + row0 + 8) * 256 + col0)   = u1;
        }
    }
}

// ---------------------------------------------------------------------------
// Main: one CTA = 4 points (M=128), N=256, 256 thr, 8 warps, 64x64 tiles.
// Gather F rows by idx + W2 (4 cp.async groups up front), fp32 rank-3 rel
// update + bias + relu in place, 2 GEMM2 rounds, maxpool.
// ---------------------------------------------------------------------------
__global__ void __launch_bounds__(256, 1)
tc_mlp2(float* __restrict__ out)
{
    extern __shared__ char smem[];
    uint32_t sb = s2u(smem);
    int tid  = threadIdx.x;
    int lane = tid & 31;
    int w    = tid >> 5;
    int mh   = w >> 2;
    int nq   = w & 3;
    int blk  = blockIdx.x;
    int bb   = blk >> 8;
    int nbase = (blk & 255) * 4;

    float* wr4s   = (float*)(smem + SM_WR);
    float* bias2s = (float*)(smem + SM_B2);
    float* rels   = (float*)(smem + SM_REL);
    int*   lidx   = (int*)(smem + SM_LIDX);

    if (tid < 128) {
        lidx[tid] = d_idx[blk * 128 + tid];
        rels[tid * 4 + 0] = d_rel[(blk * 128 + tid) * 3 + 0];
        rels[tid * 4 + 1] = d_rel[(blk * 128 + tid) * 3 + 1];
        rels[tid * 4 + 2] = d_rel[(blk * 128 + tid) * 3 + 2];
        rels[tid * 4 + 3] = 0.f;
    }
    *(float4*)(wr4s + tid * 4) = *(const float4*)(d_wr4 + tid * 4);
    bias2s[tid] = d_bias2[tid];
    __syncthreads();

    // ---- issue all copies: gather c0, gather c1, W2 c0, W2 c1 ----
    const char* Fb = (const char*)d_F;
    #pragma unroll
    for (int half = 0; half < 2; half++) {
        #pragma unroll
        for (int it = 0; it < 8; it++) {
            int e = tid + it * 256;            // 128 rows x 256B per half
            int r = e >> 4, q = e & 15;
            uint32_t dst = sb + SM_A2 + (uint32_t)(r * A2ROWB + half * 256 + q * 16);
            const char* srcb = Fb + (size_t)(bb * 1024 + lidx[r]) * 512 + half * 256 + q * 16;
            cpa16(dst, srcb);
        }
        CP_COMMIT();
    }
    #pragma unroll
    for (int t = 0; t < 2; t++) {
        #pragma unroll
        for (int it = 0; it < 16; it++) {
            int e = tid + it * 256;            // 256 rows x 256B
            int o = e >> 4, q = e & 15;
            uint32_t dst = sb + SM_W + (uint32_t)(t * WBUF + o * KROWB + q * 16);
            const char* srcb = (const char*)d_w2 + (size_t)t * 65536 + o * 256 + q * 16;
            cpa16(dst, srcb);
        }
        CP_COMMIT();
    }

    // ---- wait gathers; rank-3 rel update + bias + relu, in place ----
    CP_WAITG(2);
    __syncthreads();
    {
        int tp = tid & 127;                    // column pair index
        int rh = tid >> 7;                     // row half (64 rows each)
        int c0 = tp * 2;
        float4 wa  = *(float4*)(wr4s + c0 * 4);
        float4 wb4 = *(float4*)(wr4s + (c0 + 1) * 4);
        char* base = smem + SM_A2 + c0 * 2;
        #pragma unroll 4
        for (int i = 0; i < 64; i++) {
            int r = rh * 64 + i;
            uint32_t* addr = (uint32_t*)(base + r * A2ROWB);
            uint32_t u = *addr;
            float f0 = __half2float(__ushort_as_half((unsigned short)(u & 0xffff)));
            float f1 = __half2float(__ushort_as_half((unsigned short)(u >> 16)));
            float4 r4 = *(float4*)(rels + r * 4);
            float y0 = f0 + r4.x * wa.x  + r4.y * wa.y  + r4.z * wa.z  + wa.w;
            float y1 = f1 + r4.x * wb4.x + r4.y * wb4.y + r4.z * wb4.z + wb4.w;
            unsigned short h0 = __half_as_ushort(__float2half_rn(fmaxf(y0, 0.f)));
            unsigned short h1 = __half_as_ushort(__float2half_rn(fmaxf(y1, 0.f)));
            *addr = h0 | ((uint32_t)h1 << 16);
        }
    }

    uint32_t a2_off = (uint32_t)((mh * 64 + (lane & 15)) * A2ROWB + (lane >> 4) * 16);
    uint32_t w_off  = (uint32_t)((nq * 64 + (lane & 7) + ((lane >> 4) << 3)) * KROWB
                                 + ((lane >> 3) & 1) * 16);

    float4 acc[4][8];
    #pragma unroll
    for (int mt = 0; mt < 4; mt++)
        #pragma unroll
        for (int nt = 0; nt < 8; nt++) acc[mt][nt] = make_float4(0.f, 0.f, 0.f, 0.f);

    // ---- GEMM2 chunk 0 ----
    CP_WAITG(1);
    __syncthreads();
    gemm_round<A2ROWB>(acc, sb + SM_A2 + a2_off, sb + SM_W + w_off);

    // ---- GEMM2 chunk 1 ----
    CP_WAITG(0);
    __syncthreads();
    gemm_round<A2ROWB>(acc, sb + SM_A2 + a2_off + 256, sb + SM_W + WBUF + w_off);

    // ---- maxpool over 32 samples + bias + relu ----
    #pragma unroll
    for (int nt = 0; nt < 8; nt++) {
        float4 c0 = acc[0][nt], c1 = acc[1][nt], c2 = acc[2][nt], c3 = acc[3][nt];
        float p0a = fmaxf(fmaxf(c0.x, c0.z), fmaxf(c1.x, c1.z));
        float p0b = fmaxf(fmaxf(c0.y, c0.w), fmaxf(c1.y, c1.w));
        float p1a = fmaxf(fmaxf(c2.x, c2.z), fmaxf(c3.x, c3.z));
        float p1b = fmaxf(fmaxf(c2.y, c2.w), fmaxf(c3.y, c3.w));
        #pragma unroll
        for (int off = 4; off < 32; off <<= 1) {
            p0a = fmaxf(p0a, __shfl_xor_sync(0xffffffffu, p0a, off));
            p0b = fmaxf(p0b, __shfl_xor_sync(0xffffffffu, p0b, off));
            p1a = fmaxf(p1a, __shfl_xor_sync(0xffffffffu, p1a, off));
            p1b = fmaxf(p1b, __shfl_xor_sync(0xffffffffu, p1b, off));
        }
        if (lane < 4) {
            int col0 = nq * 64 + nt * 8 + lane * 2;
            int n0 = nbase + mh * 2;
            float bA = bias2s[col0], bB = bias2s[col0 + 1];
            out[((size_t)bb * 256 + col0)     * 1024 + n0]     = fmaxf(p0a + bA, 0.f);
            out[((size_t)bb * 256 + col0 + 1) * 1024 + n0]     = fmaxf(p0b + bB, 0.f);
            out[((size_t)bb * 256 + col0)     * 1024 + n0 + 1] = fmaxf(p1a + bA, 0.f);
            out[((size_t)bb * 256 + col0 + 1) * 1024 + n0 + 1] = fmaxf(p1b + bB, 0.f);
        }
    }
}

// ---------------------------------------------------------------------------
extern "C" void kernel_launch(void* const* d_in, const int* in_sizes, int n_in,
                              void* d_out, int out_size)
{
    const float* xyz  = (const float*)d_in[0];
    const float* feat = (const float*)d_in[1];
    const float* rot  = (const float*)d_in[2];
    const float* w1   = (const float*)d_in[3];
    const float* g1   = (const float*)d_in[4];
    const float* b1   = (const float*)d_in[5];
    const float* m1   = (const float*)d_in[6];
    const float* v1   = (const float*)d_in[7];
    const float* w2   = (const float*)d_in[8];
    const float* g2   = (const float*)d_in[9];
    const float* b2   = (const float*)d_in[10];
    const float* m2   = (const float*)d_in[11];
    const float* v2   = (const float*)d_in[12];
    float* out = (float*)d_out;

    cudaFuncSetAttribute(f_gemm,  cudaFuncAttributeMaxDynamicSharedMemorySize, FG_TOTAL);
    cudaFuncSetAttribute(tc_mlp2, cudaFuncAttributeMaxDynamicSharedMemorySize, SM_TOTAL);

    int prep_total = (CH1 + 2) * 256 * 128;      // 196608
    prep_w<<<(prep_total + 255) / 256, 256>>>(w1, g1, b1, m1, v1,
                                              w2, g2, b2, m2, v2);
    transpose_feat<<<dim3(Nc / 32, CIN / 32, Bc), dim3(32, 8)>>>(feat);
    cylinder_query<<<(Bc * Nc) / 4, 128>>>(xyz, rot);
    f_gemm<<<Bc * Nc / 128, 256, FG_TOTAL>>>();
    tc_mlp2<<<Bc * Nc / 4, 256, SM_TOTAL>>>(out);
}

// round 12
// speedup vs baseline: 1.9968x; 1.1303x over previous
#include <cuda_runtime.h>
#include <cuda_fp16.h>
#include <cstdint>

// ---------------------------------------------------------------------------
// CloudCrop R12: F = W1f·feat factored through the gather (R11) +
//   f_gemm split to 64 CTAs (M=64) for SM coverage, and
//   persistent tc_mlp3 (grid=148): W2 loaded once per CTA, loop over blocks.
// ---------------------------------------------------------------------------

#define Bc 4
#define Nc 1024
#define NS 32
#define CIN 512
#define C0 515
#define RADIUSf 0.05f
#define HMINf (-0.02f)
#define HMAXf 0.04f

#define KROWB 272             // GEMM tile row bytes (128 fp16 + 16B pad)
#define CH1 4                 // f_gemm K chunks (K=512)
#define A2ROWB 528            // A2 / y1 row bytes (256 fp16 + 16B pad)
#define FGABUF 17408          // f_gemm A tile: 64 rows * 272B
#define WBUF  69632           // W tile: 256 rows * 272B

// f_gemm smem: A 2x17408 @0, W 2x69632 @34816 -> 174080
#define FG_A1    0
#define FG_W     34816
#define FG_TOTAL 174080

// tc_mlp3 smem
#define SM_A2    0            // 128 x 528 = 67584
#define SM_W     67584        // 2 x 69632 -> ends 206848 (persistent W2)
#define SM_WR    206848       // w1rel+bias1 [256][4] f32 = 4096
#define SM_B2    210944       // bias2 f32 = 1024
#define SM_REL   211968       // rel [128][4] f32 = 2048
#define SM_LIDX  214016       // 128 ints = 512
#define SM_TOTAL 214528

// __device__ scratch (allocation-free), 16B-aligned
__device__ __align__(16) unsigned short d_fh[Bc * Nc * CIN];    // feat fp16 [p][c]
__device__ __align__(16) unsigned short d_F[Bc * Nc * 256];     // W1f·feat fp16 [p][o]
__device__ __align__(16) int            d_idx[Bc * Nc * NS];
__device__ __align__(16) float          d_rel[Bc * Nc * NS * 3];
__device__ __align__(16) unsigned short d_w1[CH1 * 256 * 128];  // [t][o][128] fp16
__device__ __align__(16) unsigned short d_w2[2 * 256 * 128];
__device__ __align__(16) float          d_wr4[256 * 4];         // {wr0,wr1,wr2,bias1}
__device__ __align__(16) float          d_bias2[256];

__device__ __forceinline__ uint32_t s2u(const void* p) {
    uint32_t a;
    asm("{ .reg .u64 t; cvta.to.shared.u64 t, %1; cvt.u32.u64 %0, t; }" : "=r"(a) : "l"(p));
    return a;
}
__device__ __forceinline__ void cpa16(uint32_t dst, const void* src) {
    asm volatile("cp.async.cg.shared.global [%0], [%1], 16;" :: "r"(dst), "l"(src));
}
#define CP_COMMIT()  asm volatile("cp.async.commit_group;" ::: "memory")
#define CP_WAITG(n)  asm volatile("cp.async.wait_group %0;" :: "n"(n) : "memory")

__device__ __forceinline__ void ldsm4(uint32_t& r0, uint32_t& r1, uint32_t& r2, uint32_t& r3,
                                      uint32_t addr) {
    asm volatile("ldmatrix.sync.aligned.m8n8.x4.shared.b16 {%0,%1,%2,%3}, [%4];"
                 : "=r"(r0), "=r"(r1), "=r"(r2), "=r"(r3) : "r"(addr));
}
#define MMA(d, A, b0r, b1r) \
    asm volatile("mma.sync.aligned.m16n8k16.row.col.f32.f16.f16.f32 " \
                 "{%0,%1,%2,%3},{%4,%5,%6,%7},{%8,%9},{%0,%1,%2,%3};" \
                 : "+f"((d).x), "+f"((d).y), "+f"((d).z), "+f"((d).w) \
                 : "r"((A)[0]), "r"((A)[1]), "r"((A)[2]), "r"((A)[3]), \
                   "r"(b0r), "r"(b1r))

// K=128 round, 64x64 warp tile (tc_mlp3): 8 ksteps x (4+4 ldsm, 32 HMMA)
template<int AROW>
__device__ __forceinline__ void gemm_round(float4 (&acc)[4][8], uint32_t a, uint32_t wb)
{
    #pragma unroll
    for (int kk = 0; kk < 8; kk++) {
        uint32_t Ax[4][4], Bf[4][4];
        uint32_t ak = a + kk * 32, wk = wb + kk * 32;
        #pragma unroll
        for (int mt = 0; mt < 4; mt++)
            ldsm4(Ax[mt][0], Ax[mt][1], Ax[mt][2], Ax[mt][3], ak + mt * 16 * AROW);
        #pragma unroll
        for (int p = 0; p < 4; p++)
            ldsm4(Bf[p][0], Bf[p][1], Bf[p][2], Bf[p][3], wk + p * 16 * KROWB);
        #pragma unroll
        for (int mt = 0; mt < 4; mt++) {
            #pragma unroll
            for (int p = 0; p < 4; p++) {
                MMA(acc[mt][2*p],   Ax[mt], Bf[p][0], Bf[p][1]);
                MMA(acc[mt][2*p+1], Ax[mt], Bf[p][2], Bf[p][3]);
            }
        }
    }
}

// K=128 round, 64x32 warp tile (f_gemm)
__device__ __forceinline__ void gemm_round64(float4 (&acc)[4][4], uint32_t a, uint32_t wb)
{
    #pragma unroll
    for (int kk = 0; kk < 8; kk++) {
        uint32_t Ax[4][4], Bf[2][4];
        uint32_t ak = a + kk * 32, wk = wb + kk * 32;
        #pragma unroll
        for (int mt = 0; mt < 4; mt++)
            ldsm4(Ax[mt][0], Ax[mt][1], Ax[mt][2], Ax[mt][3], ak + mt * 16 * KROWB);
        #pragma unroll
        for (int p = 0; p < 2; p++)
            ldsm4(Bf[p][0], Bf[p][1], Bf[p][2], Bf[p][3], wk + p * 16 * KROWB);
        #pragma unroll
        for (int mt = 0; mt < 4; mt++) {
            #pragma unroll
            for (int p = 0; p < 2; p++) {
                MMA(acc[mt][2*p],   Ax[mt], Bf[p][0], Bf[p][1]);
                MMA(acc[mt][2*p+1], Ax[mt], Bf[p][2], Bf[p][3]);
            }
        }
    }
}

// ---------------------------------------------------------------------------
__global__ void prep_w(const float* __restrict__ w1,
                       const float* __restrict__ g1, const float* __restrict__ b1,
                       const float* __restrict__ m1, const float* __restrict__ v1,
                       const float* __restrict__ w2,
                       const float* __restrict__ g2, const float* __restrict__ b2,
                       const float* __restrict__ m2, const float* __restrict__ v2)
{
    int i = blockIdx.x * blockDim.x + threadIdx.x;
    const int W1E = CH1 * 256 * 128;  // 131072
    const int W2E = 2 * 256 * 128;    // 65536
    if (i < W1E) {
        int t = i >> 15, rem = i & 32767, o = rem >> 7, k = rem & 127;
        int c = t * 128 + k;
        float s = g1[o] * rsqrtf(v1[o] + 1e-5f);
        d_w1[i] = __half_as_ushort(__float2half_rn(w1[o * C0 + c + 3] * s));
    }
    int j = i - W1E;
    if (j >= 0 && j < W2E) {
        int t = j >> 15, rem = j & 32767, o = rem >> 7, k = rem & 127;
        float s = g2[o] * rsqrtf(v2[o] + 1e-5f);
        d_w2[j] = __half_as_ushort(__float2half_rn(w2[o * 256 + t * 128 + k] * s));
    }
    if (i < 256) {
        float s1 = g1[i] * rsqrtf(v1[i] + 1e-5f);
        d_wr4[i * 4 + 0] = w1[i * C0 + 0] * s1;
        d_wr4[i * 4 + 1] = w1[i * C0 + 1] * s1;
        d_wr4[i * 4 + 2] = w1[i * C0 + 2] * s1;
        d_wr4[i * 4 + 3] = b1[i] - m1[i] * s1;
        float s2 = g2[i] * rsqrtf(v2[i] + 1e-5f);
        d_bias2[i] = b2[i] - m2[i] * s2;
    }
}

__global__ void transpose_feat(const float* __restrict__ f)
{
    __shared__ float tile[32][33];
    int b  = blockIdx.z;
    int c0 = blockIdx.y * 32;
    int n0 = blockIdx.x * 32;
    int tx = threadIdx.x, ty = threadIdx.y;
    const float* src = f + (size_t)b * CIN * Nc;
    #pragma unroll
    for (int k = 0; k < 32; k += 8)
        tile[ty + k][tx] = src[(c0 + ty + k) * Nc + n0 + tx];
    __syncthreads();
    size_t base = (size_t)b * Nc * CIN;
    #pragma unroll
    for (int k = 0; k < 32; k += 8) {
        float v = tile[tx][ty + k];
        d_fh[base + (size_t)(n0 + ty + k) * CIN + c0 + tx] =
            __half_as_ushort(__float2half_rn(v));
    }
}

__global__ void cylinder_query(const float* __restrict__ xyz,
                               const float* __restrict__ rot)
{
    __shared__ int sidx[4][NS];
    int w    = threadIdx.x >> 5;
    int lane = threadIdx.x & 31;
    int p = blockIdx.x * 4 + w;
    int b = p >> 10, n = p & 1023;

    const float* X = xyz + (size_t)b * Nc * 3;
    float cx = X[n * 3 + 0], cy = X[n * 3 + 1], cz = X[n * 3 + 2];
    const float* R = rot + (size_t)p * 9;
    float r00 = R[0], r01 = R[1], r02 = R[2];
    float r10 = R[3], r11 = R[4], r12 = R[5];
    float r20 = R[6], r21 = R[7], r22 = R[8];
    const float R2 = RADIUSf * RADIUSf;

    int cnt = 0;
    for (int m0 = 0; m0 < Nc; m0 += 32) {
        int m = m0 + lane;
        float dx = X[m * 3 + 0] - cx;
        float dy = X[m * 3 + 1] - cy;
        float dz = X[m * 3 + 2] - cz;
        float xr = r00 * dx + r01 * dy + r02 * dz;
        float yr = r10 * dx + r11 * dy + r12 * dz;
        float zr = r20 * dx + r21 * dy + r22 * dz;
        bool mk = (yr * yr + zr * zr < R2) && (xr > HMINf) && (xr < HMAXf);
        unsigned bal = __ballot_sync(0xffffffffu, mk);
        int pre = __popc(bal & ((1u << lane) - 1u));
        int slot = cnt + pre;
        if (mk && slot < NS) sidx[w][slot] = m;
        cnt += __popc(bal);
        if (cnt >= NS) break;
    }
    __syncwarp();
    int c32 = cnt < NS ? cnt : NS;
    int pad = (cnt > 0) ? sidx[w][0] : 0;
    int j = (lane < c32) ? sidx[w][lane] : pad;

    d_idx[p * NS + lane] = j;
    float dx = X[j * 3 + 0] - cx;
    float dy = X[j * 3 + 1] - cy;
    float dz = X[j * 3 + 2] - cz;
    float inv = 1.0f / RADIUSf;
    d_rel[(p * NS + lane) * 3 + 0] = (dx * r00 + dy * r10 + dz * r20) * inv;
    d_rel[(p * NS + lane) * 3 + 1] = (dx * r01 + dy * r11 + dz * r21) * inv;
    d_rel[(p * NS + lane) * 3 + 2] = (dx * r02 + dy * r12 + dz * r22) * inv;
}

// ---------------------------------------------------------------------------
// f_gemm: F[p][o] = sum_c feat[p][c] * W1f[o][c]. 64 CTAs x (M=64, N=256,
// K=512). 8 warps, warp tile 64x32 (wn = warp).
// ---------------------------------------------------------------------------
__global__ void __launch_bounds__(256, 1)
f_gemm()
{
    extern __shared__ char smem[];
    uint32_t sb = s2u(smem);
    int tid  = threadIdx.x;
    int lane = tid & 31;
    int wn   = tid >> 5;               // N stripe: cols wn*32..
    int p0   = blockIdx.x * 64;

    uint32_t a_off = (uint32_t)(((lane & 15)) * KROWB + (lane >> 4) * 16);
    uint32_t w_off = (uint32_t)((wn * 32 + (lane & 7) + ((lane >> 4) << 3)) * KROWB
                                + ((lane >> 3) & 1) * 16);

    auto issue = [&](int t) {
        int buf = t & 1;
        #pragma unroll
        for (int it = 0; it < 4; it++) {
            int e = tid + it * 256;            // A: 64 rows x 256B -> 1024 ops
            int r = e >> 4, q = e & 15;
            uint32_t dst = sb + FG_A1 + (uint32_t)(buf * FGABUF + r * KROWB + q * 16);
            const char* srcb = (const char*)d_fh + (size_t)(p0 + r) * 1024 + t * 256 + q * 16;
            cpa16(dst, srcb);
        }
        #pragma unroll
        for (int it = 0; it < 16; it++) {
            int e = tid + it * 256;            // W: 256 rows x 256B
            int o = e >> 4, q = e & 15;
            uint32_t dst = sb + FG_W + (uint32_t)(buf * WBUF + o * KROWB + q * 16);
            const char* srcb = (const char*)d_w1 + (size_t)t * 65536 + o * 256 + q * 16;
            cpa16(dst, srcb);
        }
        CP_COMMIT();
    };

    float4 acc[4][4];
    #pragma unroll
    for (int mt = 0; mt < 4; mt++)
        #pragma unroll
        for (int nt = 0; nt < 4; nt++) acc[mt][nt] = make_float4(0.f, 0.f, 0.f, 0.f);

    issue(0);
    for (int t = 0; t < CH1; t++) {
        int buf = t & 1;
        CP_WAITG(0);
        __syncthreads();
        if (t + 1 < CH1) issue(t + 1);
        gemm_round64(acc,
            sb + FG_A1 + (uint32_t)(buf * FGABUF) + a_off,
            sb + FG_W  + (uint32_t)(buf * WBUF)  + w_off);
    }

    // write F fp16 (raw accumulators)
    #pragma unroll
    for (int mt = 0; mt < 4; mt++) {
        int row0 = mt * 16 + (lane >> 2);
        #pragma unroll
        for (int nt = 0; nt < 4; nt++) {
            int col0 = wn * 32 + nt * 8 + (lane & 3) * 2;
            float4 c = acc[mt][nt];
            uint32_t u0 = __half_as_ushort(__float2half_rn(c.x))
                        | ((uint32_t)__half_as_ushort(__float2half_rn(c.y)) << 16);
            uint32_t u1 = __half_as_ushort(__float2half_rn(c.z))
                        | ((uint32_t)__half_as_ushort(__float2half_rn(c.w)) << 16);
            *(uint32_t*)(d_F + (size_t)(p0 + row0) * 256 + col0)     = u0;
            *(uint32_t*)(d_F + (size_t)(p0 + row0 + 8) * 256 + col0) = u1;
        }
    }
}

// ---------------------------------------------------------------------------
// tc_mlp3 (persistent): grid=148. W2 loaded once; loop over point-blocks:
// gather F + rank-3 rel update + bias + relu -> 2 GEMM rounds -> maxpool.
// Next block's gather issued before the current maxpool to overlap.
// ---------------------------------------------------------------------------
__global__ void __launch_bounds__(256, 1)
tc_mlp3(float* __restrict__ out)
{
    extern __shared__ char smem[];
    uint32_t sb = s2u(smem);
    int tid  = threadIdx.x;
    int lane = tid & 31;
    int w    = tid >> 5;
    int mh   = w >> 2;
    int nq   = w & 3;

    float* wr4s   = (float*)(smem + SM_WR);
    float* bias2s = (float*)(smem + SM_B2);
    float* rels   = (float*)(smem + SM_REL);
    int*   lidx   = (int*)(smem + SM_LIDX);

    *(float4*)(wr4s + tid * 4) = *(const float4*)(d_wr4 + tid * 4);
    bias2s[tid] = d_bias2[tid];

    // persistent W2: both K chunks, loaded once
    #pragma unroll
    for (int t = 0; t < 2; t++) {
        #pragma unroll
        for (int it = 0; it < 16; it++) {
            int e = tid + it * 256;
            int o = e >> 4, q = e & 15;
            uint32_t dst = sb + SM_W + (uint32_t)(t * WBUF + o * KROWB + q * 16);
            const char* srcb = (const char*)d_w2 + (size_t)t * 65536 + o * 256 + q * 16;
            cpa16(dst, srcb);
        }
        CP_COMMIT();
    }

    const char* Fb = (const char*)d_F;
    uint32_t a2_off = (uint32_t)((mh * 64 + (lane & 15)) * A2ROWB + (lane >> 4) * 16);
    uint32_t w_off  = (uint32_t)((nq * 64 + (lane & 7) + ((lane >> 4) << 3)) * KROWB
                                 + ((lane >> 3) & 1) * 16);

    auto load_meta = [&](int b) {
        if (tid < 128) {
            lidx[tid] = d_idx[b * 128 + tid];
            rels[tid * 4 + 0] = d_rel[(b * 128 + tid) * 3 + 0];
            rels[tid * 4 + 1] = d_rel[(b * 128 + tid) * 3 + 1];
            rels[tid * 4 + 2] = d_rel[(b * 128 + tid) * 3 + 2];
            rels[tid * 4 + 3] = 0.f;
        }
    };
    auto issue_gather = [&](int b) {
        #pragma unroll
        for (int half = 0; half < 2; half++) {
            #pragma unroll
            for (int it = 0; it < 8; it++) {
                int e = tid + it * 256;
                int r = e >> 4, q = e & 15;
                uint32_t dst = sb + SM_A2 + (uint32_t)(r * A2ROWB + half * 256 + q * 16);
                const char* srcb = Fb + (size_t)((b >> 8) * 1024 + lidx[r]) * 512
                                      + half * 256 + q * 16;
                cpa16(dst, srcb);
            }
        }
        CP_COMMIT();
    };

    int blk = blockIdx.x;
    if (blk < 1024) {
        load_meta(blk);
        __syncthreads();
        issue_gather(blk);
    }

    for (; blk < 1024; blk += gridDim.x) {
        CP_WAITG(0);               // gather landed (first iter: + W2)
        __syncthreads();

        // rank-3 rel update + bias + relu, in place on A2
        {
            int tp = tid & 127;
            int rh = tid >> 7;
            int c0 = tp * 2;
            float4 wa  = *(float4*)(wr4s + c0 * 4);
            float4 wb4 = *(float4*)(wr4s + (c0 + 1) * 4);
            char* base = smem + SM_A2 + c0 * 2;
            #pragma unroll 4
            for (int i = 0; i < 64; i++) {
                int r = rh * 64 + i;
                uint32_t* addr = (uint32_t*)(base + r * A2ROWB);
                uint32_t u = *addr;
                float f0 = __half2float(__ushort_as_half((unsigned short)(u & 0xffff)));
                float f1 = __half2float(__ushort_as_half((unsigned short)(u >> 16)));
                float4 r4 = *(float4*)(rels + r * 4);
                float y0 = f0 + r4.x * wa.x  + r4.y * wa.y  + r4.z * wa.z  + wa.w;
                float y1 = f1 + r4.x * wb4.x + r4.y * wb4.y + r4.z * wb4.z + wb4.w;
                unsigned short h0 = __half_as_ushort(__float2half_rn(fmaxf(y0, 0.f)));
                unsigned short h1 = __half_as_ushort(__float2half_rn(fmaxf(y1, 0.f)));
                *addr = h0 | ((uint32_t)h1 << 16);
            }
        }
        __syncthreads();

        float4 acc[4][8];
        #pragma unroll
        for (int mt = 0; mt < 4; mt++)
            #pragma unroll
            for (int nt = 0; nt < 8; nt++) acc[mt][nt] = make_float4(0.f, 0.f, 0.f, 0.f);

        gemm_round<A2ROWB>(acc, sb + SM_A2 + a2_off,        sb + SM_W + w_off);
        gemm_round<A2ROWB>(acc, sb + SM_A2 + a2_off + 256,  sb + SM_W + WBUF + w_off);

        __syncthreads();           // all warps done reading A2/rels

        int nblk = blk + gridDim.x;
        if (nblk < 1024) {         // prefetch next block's gather behind maxpool
            load_meta(nblk);
            __syncthreads();
            issue_gather(nblk);
        }

        // maxpool over 32 samples + bias + relu, store
        int bb    = blk >> 8;
        int nbase = (blk & 255) * 4;
        #pragma unroll
        for (int nt = 0; nt < 8; nt++) {
            float4 c0 = acc[0][nt], c1 = acc[1][nt], c2 = acc[2][nt], c3 = acc[3][nt];
            float p0a = fmaxf(fmaxf(c0.x, c0.z), fmaxf(c1.x, c1.z));
            float p0b = fmaxf(fmaxf(c0.y, c0.w), fmaxf(c1.y, c1.w));
            float p1a = fmaxf(fmaxf(c2.x, c2.z), fmaxf(c3.x, c3.z));
            float p1b = fmaxf(fmaxf(c2.y, c2.w), fmaxf(c3.y, c3.w));
            #pragma unroll
            for (int off = 4; off < 32; off <<= 1) {
                p0a = fmaxf(p0a, __shfl_xor_sync(0xffffffffu, p0a, off));
                p0b = fmaxf(p0b, __shfl_xor_sync(0xffffffffu, p0b, off));
                p1a = fmaxf(p1a, __shfl_xor_sync(0xffffffffu, p1a, off));
                p1b = fmaxf(p1b, __shfl_xor_sync(0xffffffffu, p1b, off));
            }
            if (lane < 4) {
                int col0 = nq * 64 + nt * 8 + lane * 2;
                int n0 = nbase + mh * 2;
                float bA = bias2s[col0], bB = bias2s[col0 + 1];
                out[((size_t)bb * 256 + col0)     * 1024 + n0]     = fmaxf(p0a + bA, 0.f);
                out[((size_t)bb * 256 + col0 + 1) * 1024 + n0]     = fmaxf(p0b + bB, 0.f);
                out[((size_t)bb * 256 + col0)     * 1024 + n0 + 1] = fmaxf(p1a + bA, 0.f);
                out[((size_t)bb * 256 + col0 + 1) * 1024 + n0 + 1] = fmaxf(p1b + bB, 0.f);
            }
        }
    }
}

// ---------------------------------------------------------------------------
extern "C" void kernel_launch(void* const* d_in, const int* in_sizes, int n_in,
                              void* d_out, int out_size)
{
    const float* xyz  = (const float*)d_in[0];
    const float* feat = (const float*)d_in[1];
    const float* rot  = (const float*)d_in[2];
    const float* w1   = (const float*)d_in[3];
    const float* g1   = (const float*)d_in[4];
    const float* b1   = (const float*)d_in[5];
    const float* m1   = (const float*)d_in[6];
    const float* v1   = (const float*)d_in[7];
    const float* w2   = (const float*)d_in[8];
    const float* g2   = (const float*)d_in[9];
    const float* b2   = (const float*)d_in[10];
    const float* m2   = (const float*)d_in[11];
    const float* v2   = (const float*)d_in[12];
    float* out = (float*)d_out;

    cudaFuncSetAttribute(f_gemm,  cudaFuncAttributeMaxDynamicSharedMemorySize, FG_TOTAL);
    cudaFuncSetAttribute(tc_mlp3, cudaFuncAttributeMaxDynamicSharedMemorySize, SM_TOTAL);

    int prep_total = (CH1 + 2) * 256 * 128;      // 196608
    prep_w<<<(prep_total + 255) / 256, 256>>>(w1, g1, b1, m1, v1,
                                              w2, g2, b2, m2, v2);
    transpose_feat<<<dim3(Nc / 32, CIN / 32, Bc), dim3(32, 8)>>>(feat);
    cylinder_query<<<(Bc * Nc) / 4, 128>>>(xyz, rot);
    f_gemm<<<Bc * Nc / 64, 256, FG_TOTAL>>>();
    tc_mlp3<<<148, 256, SM_TOTAL>>>(out);
}

// round 15
// speedup vs baseline: 2.0635x; 1.0334x over previous
#include <cuda_runtime.h>
#include <cuda_fp16.h>
#include <cstdint>

// ---------------------------------------------------------------------------
// CloudCrop R15: R12 (measured 108.8us) with ONLY f_gemm re-tiled to grid=128
// (64 points x 128 cols per CTA, 32x32 warp tiles). tc_mlp3 is R12 verbatim.
// ---------------------------------------------------------------------------

#define Bc 4
#define Nc 1024
#define NS 32
#define CIN 512
#define C0 515
#define RADIUSf 0.05f
#define HMINf (-0.02f)
#define HMAXf 0.04f

#define KROWB 272             // GEMM tile row bytes (128 fp16 + 16B pad)
#define CH1 4                 // f_gemm K chunks (K=512)
#define A2ROWB 528            // A2 / y1 row bytes (256 fp16 + 16B pad)
#define FGABUF 17408          // f_gemm A tile: 64 rows * 272B
#define FGWBUF 34816          // f_gemm W tile: 128 rows * 272B
#define WBUF  69632           // tc_mlp3 W tile: 256 rows * 272B

// f_gemm smem: A 2x17408 @0, W 2x34816 @34816 -> 104448
#define FG_A1    0
#define FG_W     34816
#define FG_TOTAL 104448

// tc_mlp3 smem (identical to R12)
#define SM_A2    0            // 128 x 528 = 67584
#define SM_W     67584        // 2 x 69632 -> ends 206848 (persistent W2)
#define SM_WR    206848       // w1rel+bias1 [256][4] f32 = 4096
#define SM_B2    210944       // bias2 f32 = 1024
#define SM_REL   211968       // rel [128][4] f32 = 2048
#define SM_LIDX  214016       // 128 ints = 512
#define SM_TOTAL 214528

// __device__ scratch (allocation-free), 16B-aligned
__device__ __align__(16) unsigned short d_fh[Bc * Nc * CIN];    // feat fp16 [p][c]
__device__ __align__(16) unsigned short d_F[Bc * Nc * 256];     // W1f·feat fp16 [p][o]
__device__ __align__(16) int            d_idx[Bc * Nc * NS];
__device__ __align__(16) float          d_rel[Bc * Nc * NS * 3];
__device__ __align__(16) unsigned short d_w1[CH1 * 256 * 128];  // [t][o][128] fp16
__device__ __align__(16) unsigned short d_w2[2 * 256 * 128];
__device__ __align__(16) float          d_wr4[256 * 4];         // {wr0,wr1,wr2,bias1}
__device__ __align__(16) float          d_bias2[256];

__device__ __forceinline__ uint32_t s2u(const void* p) {
    uint32_t a;
    asm("{ .reg .u64 t; cvta.to.shared.u64 t, %1; cvt.u32.u64 %0, t; }" : "=r"(a) : "l"(p));
    return a;
}
__device__ __forceinline__ void cpa16(uint32_t dst, const void* src) {
    asm volatile("cp.async.cg.shared.global [%0], [%1], 16;" :: "r"(dst), "l"(src));
}
#define CP_COMMIT()  asm volatile("cp.async.commit_group;" ::: "memory")
#define CP_WAITG(n)  asm volatile("cp.async.wait_group %0;" :: "n"(n) : "memory")

__device__ __forceinline__ void ldsm4(uint32_t& r0, uint32_t& r1, uint32_t& r2, uint32_t& r3,
                                      uint32_t addr) {
    asm volatile("ldmatrix.sync.aligned.m8n8.x4.shared.b16 {%0,%1,%2,%3}, [%4];"
                 : "=r"(r0), "=r"(r1), "=r"(r2), "=r"(r3) : "r"(addr));
}
#define MMA(d, A, b0r, b1r) \
    asm volatile("mma.sync.aligned.m16n8k16.row.col.f32.f16.f16.f32 " \
                 "{%0,%1,%2,%3},{%4,%5,%6,%7},{%8,%9},{%0,%1,%2,%3};" \
                 : "+f"((d).x), "+f"((d).y), "+f"((d).z), "+f"((d).w) \
                 : "r"((A)[0]), "r"((A)[1]), "r"((A)[2]), "r"((A)[3]), \
                   "r"(b0r), "r"(b1r))

// K=128 round, 64x64 warp tile (tc_mlp3)
template<int AROW>
__device__ __forceinline__ void gemm_round(float4 (&acc)[4][8], uint32_t a, uint32_t wb)
{
    #pragma unroll
    for (int kk = 0; kk < 8; kk++) {
        uint32_t Ax[4][4], Bf[4][4];
        uint32_t ak = a + kk * 32, wk = wb + kk * 32;
        #pragma unroll
        for (int mt = 0; mt < 4; mt++)
            ldsm4(Ax[mt][0], Ax[mt][1], Ax[mt][2], Ax[mt][3], ak + mt * 16 * AROW);
        #pragma unroll
        for (int p = 0; p < 4; p++)
            ldsm4(Bf[p][0], Bf[p][1], Bf[p][2], Bf[p][3], wk + p * 16 * KROWB);
        #pragma unroll
        for (int mt = 0; mt < 4; mt++) {
            #pragma unroll
            for (int p = 0; p < 4; p++) {
                MMA(acc[mt][2*p],   Ax[mt], Bf[p][0], Bf[p][1]);
                MMA(acc[mt][2*p+1], Ax[mt], Bf[p][2], Bf[p][3]);
            }
        }
    }
}

// K=128 round, 32x32 warp tile (f_gemm)
__device__ __forceinline__ void gemm_round32(float4 (&acc)[2][4], uint32_t a, uint32_t wb)
{
    #pragma unroll
    for (int kk = 0; kk < 8; kk++) {
        uint32_t Ax[2][4], Bf[2][4];
        uint32_t ak = a + kk * 32, wk = wb + kk * 32;
        #pragma unroll
        for (int mt = 0; mt < 2; mt++)
            ldsm4(Ax[mt][0], Ax[mt][1], Ax[mt][2], Ax[mt][3], ak + mt * 16 * KROWB);
        #pragma unroll
        for (int p = 0; p < 2; p++)
            ldsm4(Bf[p][0], Bf[p][1], Bf[p][2], Bf[p][3], wk + p * 16 * KROWB);
        #pragma unroll
        for (int mt = 0; mt < 2; mt++) {
            #pragma unroll
            for (int p = 0; p < 2; p++) {
                MMA(acc[mt][2*p],   Ax[mt], Bf[p][0], Bf[p][1]);
                MMA(acc[mt][2*p+1], Ax[mt], Bf[p][2], Bf[p][3]);
            }
        }
    }
}

// ---------------------------------------------------------------------------
__global__ void prep_w(const float* __restrict__ w1,
                       const float* __restrict__ g1, const float* __restrict__ b1,
                       const float* __restrict__ m1, const float* __restrict__ v1,
                       const float* __restrict__ w2,
                       const float* __restrict__ g2, const float* __restrict__ b2,
                       const float* __restrict__ m2, const float* __restrict__ v2)
{
    int i = blockIdx.x * blockDim.x + threadIdx.x;
    const int W1E = CH1 * 256 * 128;  // 131072
    const int W2E = 2 * 256 * 128;    // 65536
    if (i < W1E) {
        int t = i >> 15, rem = i & 32767, o = rem >> 7, k = rem & 127;
        int c = t * 128 + k;
        float s = g1[o] * rsqrtf(v1[o] + 1e-5f);
        d_w1[i] = __half_as_ushort(__float2half_rn(w1[o * C0 + c + 3] * s));
    }
    int j = i - W1E;
    if (j >= 0 && j < W2E) {
        int t = j >> 15, rem = j & 32767, o = rem >> 7, k = rem & 127;
        float s = g2[o] * rsqrtf(v2[o] + 1e-5f);
        d_w2[j] = __half_as_ushort(__float2half_rn(w2[o * 256 + t * 128 + k] * s));
    }
    if (i < 256) {
        float s1 = g1[i] * rsqrtf(v1[i] + 1e-5f);
        d_wr4[i * 4 + 0] = w1[i * C0 + 0] * s1;
        d_wr4[i * 4 + 1] = w1[i * C0 + 1] * s1;
        d_wr4[i * 4 + 2] = w1[i * C0 + 2] * s1;
        d_wr4[i * 4 + 3] = b1[i] - m1[i] * s1;
        float s2 = g2[i] * rsqrtf(v2[i] + 1e-5f);
        d_bias2[i] = b2[i] - m2[i] * s2;
    }
}

__global__ void transpose_feat(const float* __restrict__ f)
{
    __shared__ float tile[32][33];
    int b  = blockIdx.z;
    int c0 = blockIdx.y * 32;
    int n0 = blockIdx.x * 32;
    int tx = threadIdx.x, ty = threadIdx.y;
    const float* src = f + (size_t)b * CIN * Nc;
    #pragma unroll
    for (int k = 0; k < 32; k += 8)
        tile[ty + k][tx] = src[(c0 + ty + k) * Nc + n0 + tx];
    __syncthreads();
    size_t base = (size_t)b * Nc * CIN;
    #pragma unroll
    for (int k = 0; k < 32; k += 8) {
        float v = tile[tx][ty + k];
        d_fh[base + (size_t)(n0 + ty + k) * CIN + c0 + tx] =
            __half_as_ushort(__float2half_rn(v));
    }
}

__global__ void cylinder_query(const float* __restrict__ xyz,
                               const float* __restrict__ rot)
{
    __shared__ int sidx[4][NS];
    int w    = threadIdx.x >> 5;
    int lane = threadIdx.x & 31;
    int p = blockIdx.x * 4 + w;
    int b = p >> 10, n = p & 1023;

    const float* X = xyz + (size_t)b * Nc * 3;
    float cx = X[n * 3 + 0], cy = X[n * 3 + 1], cz = X[n * 3 + 2];
    const float* R = rot + (size_t)p * 9;
    float r00 = R[0], r01 = R[1], r02 = R[2];
    float r10 = R[3], r11 = R[4], r12 = R[5];
    float r20 = R[6], r21 = R[7], r22 = R[8];
    const float R2 = RADIUSf * RADIUSf;

    int cnt = 0;
    for (int m0 = 0; m0 < Nc; m0 += 32) {
        int m = m0 + lane;
        float dx = X[m * 3 + 0] - cx;
        float dy = X[m * 3 + 1] - cy;
        float dz = X[m * 3 + 2] - cz;
        float xr = r00 * dx + r01 * dy + r02 * dz;
        float yr = r10 * dx + r11 * dy + r12 * dz;
        float zr = r20 * dx + r21 * dy + r22 * dz;
        bool mk = (yr * yr + zr * zr < R2) && (xr > HMINf) && (xr < HMAXf);
        unsigned bal = __ballot_sync(0xffffffffu, mk);
        int pre = __popc(bal & ((1u << lane) - 1u));
        int slot = cnt + pre;
        if (mk && slot < NS) sidx[w][slot] = m;
        cnt += __popc(bal);
        if (cnt >= NS) break;
    }
    __syncwarp();
    int c32 = cnt < NS ? cnt : NS;
    int pad = (cnt > 0) ? sidx[w][0] : 0;
    int j = (lane < c32) ? sidx[w][lane] : pad;

    d_idx[p * NS + lane] = j;
    float dx = X[j * 3 + 0] - cx;
    float dy = X[j * 3 + 1] - cy;
    float dz = X[j * 3 + 2] - cz;
    float inv = 1.0f / RADIUSf;
    d_rel[(p * NS + lane) * 3 + 0] = (dx * r00 + dy * r10 + dz * r20) * inv;
    d_rel[(p * NS + lane) * 3 + 1] = (dx * r01 + dy * r11 + dz * r21) * inv;
    d_rel[(p * NS + lane) * 3 + 2] = (dx * r02 + dy * r12 + dz * r22) * inv;
}

// ---------------------------------------------------------------------------
// f_gemm: F[p][o] = sum_c feat[p][c] * W1f[o][c]  (raw, no bias/relu).
// grid=128: CTA = (pblk 64 rows) x (nh 128 cols), K=512. Warp tile 32x32.
// ---------------------------------------------------------------------------
__global__ void __launch_bounds__(256, 1)
f_gemm()
{
    extern __shared__ char smem[];
    uint32_t sb = s2u(smem);
    int tid  = threadIdx.x;
    int lane = tid & 31;
    int w    = tid >> 5;
    int mh2  = w >> 2;                 // 0/1: rows 32
    int nq   = w & 3;                  // cols 32
    int p0   = (blockIdx.x >> 1) * 64;
    int nh   = blockIdx.x & 1;         // N half (128 cols)

    uint32_t a_off = (uint32_t)((mh2 * 32 + (lane & 15)) * KROWB + (lane >> 4) * 16);
    uint32_t w_off = (uint32_t)((nq * 32 + (lane & 7) + ((lane >> 4) << 3)) * KROWB
                                + ((lane >> 3) & 1) * 16);

    auto issue = [&](int t) {
        int buf = t & 1;
        #pragma unroll
        for (int it = 0; it < 4; it++) {
            int e = tid + it * 256;            // A: 64 rows x 16 x 16B
            int r = e >> 4, q = e & 15;
            uint32_t dst = sb + FG_A1 + (uint32_t)(buf * FGABUF + r * KROWB + q * 16);
            const char* srcb = (const char*)d_fh + (size_t)(p0 + r) * 1024 + t * 256 + q * 16;
            cpa16(dst, srcb);
        }
        #pragma unroll
        for (int it = 0; it < 8; it++) {
            int e = tid + it * 256;            // W: 128 rows x 16 x 16B
            int o = e >> 4, q = e & 15;
            uint32_t dst = sb + FG_W + (uint32_t)(buf * FGWBUF + o * KROWB + q * 16);
            const char* srcb = (const char*)d_w1 + (size_t)t * 65536
                             + (size_t)(nh * 128 + o) * 256 + q * 16;
            cpa16(dst, srcb);
        }
        CP_COMMIT();
    };

    float4 acc[2][4];
    #pragma unroll
    for (int mt = 0; mt < 2; mt++)
        #pragma unroll
        for (int nt = 0; nt < 4; nt++) acc[mt][nt] = make_float4(0.f, 0.f, 0.f, 0.f);

    issue(0);
    for (int t = 0; t < CH1; t++) {
        int buf = t & 1;
        CP_WAITG(0);
        __syncthreads();
        if (t + 1 < CH1) issue(t + 1);
        gemm_round32(acc,
            sb + FG_A1 + (uint32_t)(buf * FGABUF) + a_off,
            sb + FG_W  + (uint32_t)(buf * FGWBUF) + w_off);
    }

    // write F fp16 (raw accumulators)
    #pragma unroll
    for (int mt = 0; mt < 2; mt++) {
        int row0 = mh2 * 32 + mt * 16 + (lane >> 2);
        #pragma unroll
        for (int nt = 0; nt < 4; nt++) {
            int cl = nq * 32 + nt * 8 + (lane & 3) * 2;   // local col
            float4 c = acc[mt][nt];
            uint32_t u0 = __half_as_ushort(__float2half_rn(c.x))
                        | ((uint32_t)__half_as_ushort(__float2half_rn(c.y)) << 16);
            uint32_t u1 = __half_as_ushort(__float2half_rn(c.z))
                        | ((uint32_t)__half_as_ushort(__float2half_rn(c.w)) << 16);
            *(uint32_t*)(d_F + (size_t)(p0 + row0) * 256 + nh * 128 + cl)     = u0;
            *(uint32_t*)(d_F + (size_t)(p0 + row0 + 8) * 256 + nh * 128 + cl) = u1;
        }
    }
}

// ---------------------------------------------------------------------------
// tc_mlp3 (persistent, grid=148) — R12 VERBATIM: W2 loaded once; loop over
// blocks: gather F + fp32 rank-3 rel update + bias + relu -> 2 GEMM rounds
// -> maxpool. Next block's gather issued before the maxpool.
// ---------------------------------------------------------------------------
__global__ void __launch_bounds__(256, 1)
tc_mlp3(float* __restrict__ out)
{
    extern __shared__ char smem[];
    uint32_t sb = s2u(smem);
    int tid  = threadIdx.x;
    int lane = tid & 31;
    int w    = tid >> 5;
    int mh   = w >> 2;
    int nq   = w & 3;

    float* wr4s   = (float*)(smem + SM_WR);
    float* bias2s = (float*)(smem + SM_B2);
    float* rels   = (float*)(smem + SM_REL);
    int*   lidx   = (int*)(smem + SM_LIDX);

    *(float4*)(wr4s + tid * 4) = *(const float4*)(d_wr4 + tid * 4);
    bias2s[tid] = d_bias2[tid];

    // persistent W2: both K chunks, loaded once
    #pragma unroll
    for (int t = 0; t < 2; t++) {
        #pragma unroll
        for (int it = 0; it < 16; it++) {
            int e = tid + it * 256;
            int o = e >> 4, q = e & 15;
            uint32_t dst = sb + SM_W + (uint32_t)(t * WBUF + o * KROWB + q * 16);
            const char* srcb = (const char*)d_w2 + (size_t)t * 65536 + o * 256 + q * 16;
            cpa16(dst, srcb);
        }
        CP_COMMIT();
    }

    const char* Fb = (const char*)d_F;
    uint32_t a2_off = (uint32_t)((mh * 64 + (lane & 15)) * A2ROWB + (lane >> 4) * 16);
    uint32_t w_off  = (uint32_t)((nq * 64 + (lane & 7) + ((lane >> 4) << 3)) * KROWB
                                 + ((lane >> 3) & 1) * 16);

    auto load_meta = [&](int b) {
        if (tid < 128) {
            lidx[tid] = d_idx[b * 128 + tid];
            rels[tid * 4 + 0] = d_rel[(b * 128 + tid) * 3 + 0];
            rels[tid * 4 + 1] = d_rel[(b * 128 + tid) * 3 + 1];
            rels[tid * 4 + 2] = d_rel[(b * 128 + tid) * 3 + 2];
            rels[tid * 4 + 3] = 0.f;
        }
    };
    auto issue_gather = [&](int b) {
        #pragma unroll
        for (int half = 0; half < 2; half++) {
            #pragma unroll
            for (int it = 0; it < 8; it++) {
                int e = tid + it * 256;
                int r = e >> 4, q = e & 15;
                uint32_t dst = sb + SM_A2 + (uint32_t)(r * A2ROWB + half * 256 + q * 16);
                const char* srcb = Fb + (size_t)((b >> 8) * 1024 + lidx[r]) * 512
                                      + half * 256 + q * 16;
                cpa16(dst, srcb);
            }
        }
        CP_COMMIT();
    };

    int blk = blockIdx.x;
    if (blk < 1024) {
        load_meta(blk);
        __syncthreads();
        issue_gather(blk);
    }

    for (; blk < 1024; blk += gridDim.x) {
        CP_WAITG(0);               // gather landed (first iter: + W2)
        __syncthreads();

        // rank-3 rel update + bias + relu, in place on A2
        {
            int tp = tid & 127;
            int rh = tid >> 7;
            int c0 = tp * 2;
            float4 wa  = *(float4*)(wr4s + c0 * 4);
            float4 wb4 = *(float4*)(wr4s + (c0 + 1) * 4);
            char* base = smem + SM_A2 + c0 * 2;
            #pragma unroll 4
            for (int i = 0; i < 64; i++) {
                int r = rh * 64 + i;
                uint32_t* addr = (uint32_t*)(base + r * A2ROWB);
                uint32_t u = *addr;
                float f0 = __half2float(__ushort_as_half((unsigned short)(u & 0xffff)));
                float f1 = __half2float(__ushort_as_half((unsigned short)(u >> 16)));
                float4 r4 = *(float4*)(rels + r * 4);
                float y0 = f0 + r4.x * wa.x  + r4.y * wa.y  + r4.z * wa.z  + wa.w;
                float y1 = f1 + r4.x * wb4.x + r4.y * wb4.y + r4.z * wb4.z + wb4.w;
                unsigned short h0 = __half_as_ushort(__float2half_rn(fmaxf(y0, 0.f)));
                unsigned short h1 = __half_as_ushort(__float2half_rn(fmaxf(y1, 0.f)));
                *addr = h0 | ((uint32_t)h1 << 16);
            }
        }
        __syncthreads();

        float4 acc[4][8];
        #pragma unroll
        for (int mt = 0; mt < 4; mt++)
            #pragma unroll
            for (int nt = 0; nt < 8; nt++) acc[mt][nt] = make_float4(0.f, 0.f, 0.f, 0.f);

        gemm_round<A2ROWB>(acc, sb + SM_A2 + a2_off,        sb + SM_W + w_off);
        gemm_round<A2ROWB>(acc, sb + SM_A2 + a2_off + 256,  sb + SM_W + WBUF + w_off);

        __syncthreads();           // all warps done reading A2/rels

        int nblk = blk + gridDim.x;
        if (nblk < 1024) {         // prefetch next block's gather behind maxpool
            load_meta(nblk);
            __syncthreads();
            issue_gather(nblk);
        }

        // maxpool over 32 samples + bias + relu, store
        int bb    = blk >> 8;
        int nbase = (blk & 255) * 4;
        #pragma unroll
        for (int nt = 0; nt < 8; nt++) {
            float4 c0 = acc[0][nt], c1 = acc[1][nt], c2 = acc[2][nt], c3 = acc[3][nt];
            float p0a = fmaxf(fmaxf(c0.x, c0.z), fmaxf(c1.x, c1.z));
            float p0b = fmaxf(fmaxf(c0.y, c0.w), fmaxf(c1.y, c1.w));
            float p1a = fmaxf(fmaxf(c2.x, c2.z), fmaxf(c3.x, c3.z));
            float p1b = fmaxf(fmaxf(c2.y, c2.w), fmaxf(c3.y, c3.w));
            #pragma unroll
            for (int off = 4; off < 32; off <<= 1) {
                p0a = fmaxf(p0a, __shfl_xor_sync(0xffffffffu, p0a, off));
                p0b = fmaxf(p0b, __shfl_xor_sync(0xffffffffu, p0b, off));
                p1a = fmaxf(p1a, __shfl_xor_sync(0xffffffffu, p1a, off));
                p1b = fmaxf(p1b, __shfl_xor_sync(0xffffffffu, p1b, off));
            }
            if (lane < 4) {
                int col0 = nq * 64 + nt * 8 + lane * 2;
                int n0 = nbase + mh * 2;
                float bA = bias2s[col0], bB = bias2s[col0 + 1];
                out[((size_t)bb * 256 + col0)     * 1024 + n0]     = fmaxf(p0a + bA, 0.f);
                out[((size_t)bb * 256 + col0 + 1) * 1024 + n0]     = fmaxf(p0b + bB, 0.f);
                out[((size_t)bb * 256 + col0)     * 1024 + n0 + 1] = fmaxf(p1a + bA, 0.f);
                out[((size_t)bb * 256 + col0 + 1) * 1024 + n0 + 1] = fmaxf(p1b + bB, 0.f);
            }
        }
    }
}

// ---------------------------------------------------------------------------
extern "C" void kernel_launch(void* const* d_in, const int* in_sizes, int n_in,
                              void* d_out, int out_size)
{
    const float* xyz  = (const float*)d_in[0];
    const float* feat = (const float*)d_in[1];
    const float* rot  = (const float*)d_in[2];
    const float* w1   = (const float*)d_in[3];
    const float* g1   = (const float*)d_in[4];
    const float* b1   = (const float*)d_in[5];
    const float* m1   = (const float*)d_in[6];
    const float* v1   = (const float*)d_in[7];
    const float* w2   = (const float*)d_in[8];
    const float* g2   = (const float*)d_in[9];
    const float* b2   = (const float*)d_in[10];
    const float* m2   = (const float*)d_in[11];
    const float* v2   = (const float*)d_in[12];
    float* out = (float*)d_out;

    cudaFuncSetAttribute(f_gemm,  cudaFuncAttributeMaxDynamicSharedMemorySize, FG_TOTAL);
    cudaFuncSetAttribute(tc_mlp3, cudaFuncAttributeMaxDynamicSharedMemorySize, SM_TOTAL);

    int prep_total = (CH1 + 2) * 256 * 128;      // 196608
    prep_w<<<(prep_total + 255) / 256, 256>>>(w1, g1, b1, m1, v1,
                                              w2, g2, b2, m2, v2);
    transpose_feat<<<dim3(Nc / 32, CIN / 32, Bc), dim3(32, 8)>>>(feat);
    cylinder_query<<<(Bc * Nc) / 4, 128>>>(xyz, rot);
    f_gemm<<<Bc * Nc / 32, 256, FG_TOTAL>>>();
    tc_mlp3<<<148, 256, SM_TOTAL>>>(out);
}